// round 5
// baseline (speedup 1.0000x reference)
#include <cuda_runtime.h>
#include <math.h>

#define BB   8
#define NN   16384
#define CC   64
#define HIDN 256
#define NRR  256

// ---------------- scratch (device globals; no allocs allowed) ----------------
__device__ float g_h [BB*NN*CC];    // ln1 output
__device__ float g_q [BB*NN*CC];    // q (pre-scaled by 0.125)
__device__ float g_sr[BB*NRR*CC];   // sr conv output
__device__ float g_k [BB*NRR*CC];
__device__ float g_v [BB*NRR*CC];
__device__ float g_x2[BB*NN*CC];    // x + attn-proj residual
__device__ float g_f [BB*NN*HIDN];  // fc1 output (pre dw-conv)

// ============================================================================
// K1: LN1 + q projection (warp per row). q gets *0.125 (attn scale folded in).
// ============================================================================
__global__ void k_ln1_q(const float* __restrict__ x,
                        const float* __restrict__ g1, const float* __restrict__ b1,
                        const float* __restrict__ qw, const float* __restrict__ qb) {
    __shared__ float qws[64*64];
    __shared__ float rowbuf[8][64];
    int t = threadIdx.x;
    for (int i = t; i < 4096; i += 256) qws[i] = qw[i];
    __syncthreads();
    int warp = t >> 5, lane = t & 31;
    int r = blockIdx.x * 8 + warp;             // 0 .. 131071
    const float* xr = x + r * 64;
    float a0 = xr[lane], a1 = xr[lane + 32];
    float s = a0 + a1;
#pragma unroll
    for (int o = 16; o; o >>= 1) s += __shfl_xor_sync(0xffffffffu, s, o);
    float mean = s * (1.0f/64.0f);
    float d0 = a0 - mean, d1 = a1 - mean;
    float v = d0*d0 + d1*d1;
#pragma unroll
    for (int o = 16; o; o >>= 1) v += __shfl_xor_sync(0xffffffffu, v, o);
    float inv = rsqrtf(v * (1.0f/64.0f) + 1e-5f);
    float h0 = d0 * inv * g1[lane]      + b1[lane];
    float h1 = d1 * inv * g1[lane + 32] + b1[lane + 32];
    g_h[r*64 + lane]      = h0;
    g_h[r*64 + lane + 32] = h1;
    rowbuf[warp][lane]      = h0;
    rowbuf[warp][lane + 32] = h1;
    __syncwarp();
    float acc0 = qb[lane], acc1 = qb[lane + 32];
#pragma unroll 8
    for (int ci = 0; ci < 64; ci++) {
        float hv = rowbuf[warp][ci];
        acc0 += hv * qws[ci*64 + lane];
        acc1 += hv * qws[ci*64 + lane + 32];
    }
    g_q[r*64 + lane]      = acc0 * 0.125f;
    g_q[r*64 + lane + 32] = acc1 * 0.125f;
}

// ============================================================================
// K2: spatial-reduction conv (8x8 stride 8 VALID). One block per output pos.
// 256 threads: channel c = t&63, K-split part = t>>6 (4-way) for MLP.
// ============================================================================
__global__ void k_srconv(const float* __restrict__ srw, const float* __restrict__ srb) {
    int pos = blockIdx.x;                  // b*256 + oy*16 + ox
    int b = pos >> 8; int p = pos & 255; int oy = p >> 4, ox = p & 15;
    int t = threadIdx.x;                   // 0..255
    int c = t & 63, part = t >> 6;         // 4 partial sums per channel
    __shared__ float patch[4096];          // [i*8+j][cin]
    __shared__ float red[256];
    const float* hb = g_h + (b * NN) * 64;
    for (int i = t; i < 4096; i += 256) {
        int ij = i >> 6, ci = i & 63; int ii = ij >> 3, j = ij & 7;
        patch[i] = hb[((oy*8 + ii) * 128 + ox*8 + j) * 64 + ci];
    }
    __syncthreads();
    float acc = 0.f;
    int k0 = part * 1024;
#pragma unroll 8
    for (int k = k0; k < k0 + 1024; k++) acc += patch[k] * srw[k*64 + c];
    red[t] = acc;
    __syncthreads();
    if (t < 64)
        g_sr[pos*64 + t] = srb[t] + red[t] + red[t+64] + red[t+128] + red[t+192];
}

// ============================================================================
// K3: LN over sr output + kv projection (64 -> 128). Warp per row.
// ============================================================================
__global__ void k_srn_kv(const float* __restrict__ gs, const float* __restrict__ bs,
                         const float* __restrict__ kvw, const float* __restrict__ kvb) {
    __shared__ float ws[64*128];
    __shared__ float rowbuf[8][64];
    int t = threadIdx.x;
    for (int i = t; i < 8192; i += 256) ws[i] = kvw[i];
    __syncthreads();
    int warp = t >> 5, lane = t & 31;
    int r = blockIdx.x * 8 + warp;         // 0 .. 2047
    const float* xr = g_sr + r * 64;
    float a0 = xr[lane], a1 = xr[lane + 32];
    float s = a0 + a1;
#pragma unroll
    for (int o = 16; o; o >>= 1) s += __shfl_xor_sync(0xffffffffu, s, o);
    float mean = s * (1.0f/64.0f);
    float d0 = a0 - mean, d1 = a1 - mean;
    float v = d0*d0 + d1*d1;
#pragma unroll
    for (int o = 16; o; o >>= 1) v += __shfl_xor_sync(0xffffffffu, v, o);
    float inv = rsqrtf(v * (1.0f/64.0f) + 1e-5f);
    float h0 = d0 * inv * gs[lane]      + bs[lane];
    float h1 = d1 * inv * gs[lane + 32] + bs[lane + 32];
    rowbuf[warp][lane]      = h0;
    rowbuf[warp][lane + 32] = h1;
    __syncwarp();
    float a  = kvb[lane], bq = kvb[lane+32], cv = kvb[lane+64], dv = kvb[lane+96];
#pragma unroll 8
    for (int ci = 0; ci < 64; ci++) {
        float hv = rowbuf[warp][ci];
        const float* w = ws + ci*128;
        a  += hv * w[lane];
        bq += hv * w[lane+32];
        cv += hv * w[lane+64];
        dv += hv * w[lane+96];
    }
    g_k[r*64 + lane]      = a;
    g_k[r*64 + lane + 32] = bq;
    g_v[r*64 + lane]      = cv;
    g_v[r*64 + lane + 32] = dv;
}

// ============================================================================
// K4: fused attention: QK^T (scaled q), softmax, AV, out-proj, residual.
// Block = 64 queries of one batch; all 256 keys/values resident in SMEM.
// Dynamic SMEM (floats):
//   kT [64*257]   off 0      (reused after QK: os[64*65] @0, pw[4096] @4160)
//   vs [256*64]   off 16448
//   qs [64*65]    off 32832
//   sc [64*257]   off 36992
//   rs [64]       off 53440       total 53504 floats = 214016 B
// ============================================================================
#define ATTN_SMEM_FLOATS 53504
__global__ void k_attn(const float* __restrict__ x,
                       const float* __restrict__ pwg, const float* __restrict__ pb) {
    extern __shared__ float sm[];
    float* kT = sm;
    float* vs = sm + 16448;
    float* qs = sm + 32832;
    float* sc = sm + 36992;
    float* rs = sm + 53440;
    float* os = sm;          // alias over kT (valid after QK phase)
    float* pw = sm + 4160;   // alias over kT

    int t = threadIdx.x;
    int b = blockIdx.y;
    int qtile = blockIdx.x;                // 0..255

    // load k (transposed, padded), v, q-tile
    for (int idx = t; idx < 16384; idx += 256) {
        int m = idx >> 6, c = idx & 63;
        kT[c*257 + m] = g_k[(b*256 + m)*64 + c];
        vs[idx]       = g_v[(b*256 + m)*64 + c];
    }
    for (int idx = t; idx < 4096; idx += 256) {
        int qq = idx >> 6, c = idx & 63;
        qs[qq*65 + c] = g_q[(b*NN + qtile*64 + qq)*64 + c];
    }
    __syncthreads();

    int ty = t >> 4, tx = t & 15;

    // ---- QK^T: 64q x 256k in 4 passes of 64 keys, 4x4 register tiles ----
#pragma unroll
    for (int pass = 0; pass < 4; pass++) {
        int kk0 = pass * 64;
        float acc[4][4] = {};
#pragma unroll 4
        for (int ci = 0; ci < 64; ci++) {
            float qv[4], kv[4];
#pragma unroll
            for (int r = 0; r < 4; r++) qv[r] = qs[(ty*4 + r)*65 + ci];
#pragma unroll
            for (int j = 0; j < 4; j++) kv[j] = kT[ci*257 + kk0 + tx + 16*j];
#pragma unroll
            for (int r = 0; r < 4; r++)
#pragma unroll
                for (int j = 0; j < 4; j++) acc[r][j] += qv[r]*kv[j];
        }
#pragma unroll
        for (int r = 0; r < 4; r++)
#pragma unroll
            for (int j = 0; j < 4; j++)
                sc[(ty*4 + r)*257 + kk0 + tx + 16*j] = acc[r][j];
    }
    __syncthreads();

    // ---- softmax over 256 keys; 4 threads per query row ----
    {
        int row = t >> 2, q4 = t & 3;
        float mx = -1e30f;
        for (int m = q4*64; m < q4*64 + 64; m++) mx = fmaxf(mx, sc[row*257 + m]);
        mx = fmaxf(mx, __shfl_xor_sync(0xffffffffu, mx, 1));
        mx = fmaxf(mx, __shfl_xor_sync(0xffffffffu, mx, 2));
        float sum = 0.f;
        for (int m = q4*64; m < q4*64 + 64; m++) {
            float e = expf(sc[row*257 + m] - mx);
            sc[row*257 + m] = e;
            sum += e;
        }
        sum += __shfl_xor_sync(0xffffffffu, sum, 1);
        sum += __shfl_xor_sync(0xffffffffu, sum, 2);
        if (q4 == 0) rs[row] = sum;
    }
    __syncthreads();

    // load proj weights into aliased region (kT no longer read)
    for (int i = t; i < 4096; i += 256) pw[i] = pwg[i];

    // ---- AV: 64q x 64c, K=256 ----
    {
        float acc[4][4] = {};
#pragma unroll 2
        for (int ci = 0; ci < 256; ci++) {
            float pv[4], vv[4];
#pragma unroll
            for (int r = 0; r < 4; r++) pv[r] = sc[(ty*4 + r)*257 + ci];
#pragma unroll
            for (int j = 0; j < 4; j++) vv[j] = vs[ci*64 + tx + 16*j];
#pragma unroll
            for (int r = 0; r < 4; r++)
#pragma unroll
                for (int j = 0; j < 4; j++) acc[r][j] += pv[r]*vv[j];
        }
#pragma unroll
        for (int r = 0; r < 4; r++) {
            float rinv = 1.0f / rs[ty*4 + r];
#pragma unroll
            for (int j = 0; j < 4; j++)
                os[(ty*4 + r)*65 + tx + 16*j] = acc[r][j] * rinv;
        }
    }
    __syncthreads();

    // ---- out projection + residual ----
    {
        float acc[4][4] = {};
#pragma unroll 4
        for (int ci = 0; ci < 64; ci++) {
            float ov[4], wv[4];
#pragma unroll
            for (int r = 0; r < 4; r++) ov[r] = os[(ty*4 + r)*65 + ci];
#pragma unroll
            for (int j = 0; j < 4; j++) wv[j] = pw[ci*64 + tx + 16*j];
#pragma unroll
            for (int r = 0; r < 4; r++)
#pragma unroll
                for (int j = 0; j < 4; j++) acc[r][j] += ov[r]*wv[j];
        }
#pragma unroll
        for (int r = 0; r < 4; r++) {
            int n = qtile*64 + ty*4 + r;
            int gi = (b*NN + n)*64;
#pragma unroll
            for (int j = 0; j < 4; j++) {
                int jj = tx + 16*j;
                g_x2[gi + jj] = x[gi + jj] + acc[r][j] + pb[jj];
            }
        }
    }
}

// ============================================================================
// K5: LN2 + fc1 (64 -> 256). 64-row tiles, fc1_w resident in SMEM.
// Dynamic SMEM: ws[64*256]=16384 + h2s[64*65]=4160 -> 20544 floats = 82176 B
// ============================================================================
#define FC1_SMEM_FLOATS 20544
__global__ void k_ln2_fc1(const float* __restrict__ g2, const float* __restrict__ b2,
                          const float* __restrict__ fc1w, const float* __restrict__ fc1b) {
    extern __shared__ float sm[];
    float* ws  = sm;
    float* h2s = sm + 16384;
    int t = threadIdx.x;
    for (int i = t; i < 16384; i += 256) ws[i] = fc1w[i];

    int row = t >> 2, q4 = t & 3;
    int grow = blockIdx.x*64 + row;
    float xv[16]; float s = 0.f, ss = 0.f;
    const float* xr = g_x2 + grow*64 + q4*16;
#pragma unroll
    for (int i = 0; i < 16; i++) { float v = xr[i]; xv[i] = v; s += v; ss += v*v; }
    s  += __shfl_xor_sync(0xffffffffu, s, 1);  s  += __shfl_xor_sync(0xffffffffu, s, 2);
    ss += __shfl_xor_sync(0xffffffffu, ss, 1); ss += __shfl_xor_sync(0xffffffffu, ss, 2);
    float mean = s * (1.0f/64.0f);
    float var  = ss * (1.0f/64.0f) - mean*mean;
    float inv  = rsqrtf(var + 1e-5f);
#pragma unroll
    for (int i = 0; i < 16; i++) {
        int c = q4*16 + i;
        h2s[row*65 + c] = (xv[i] - mean) * inv * g2[c] + b2[c];
    }
    __syncthreads();

    int ty = t >> 4, tx = t & 15;
#pragma unroll
    for (int pass = 0; pass < 4; pass++) {
        int j0 = pass * 64;
        float acc[4][4] = {};
#pragma unroll 4
        for (int ci = 0; ci < 64; ci++) {
            float hv[4], wv[4];
#pragma unroll
            for (int r = 0; r < 4; r++) hv[r] = h2s[(ty*4 + r)*65 + ci];
#pragma unroll
            for (int j = 0; j < 4; j++) wv[j] = ws[ci*256 + j0 + tx + 16*j];
#pragma unroll
            for (int r = 0; r < 4; r++)
#pragma unroll
                for (int j = 0; j < 4; j++) acc[r][j] += hv[r]*wv[j];
        }
#pragma unroll
        for (int r = 0; r < 4; r++) {
            int gr = blockIdx.x*64 + ty*4 + r;
#pragma unroll
            for (int j = 0; j < 4; j++) {
                int jj = j0 + tx + 16*j;
                g_f[gr*256 + jj] = acc[r][j] + fc1b[jj];
            }
        }
    }
}

// ============================================================================
// K6: depthwise 3x3 SAME + exact GELU + fc2 (256 -> 64) + residual -> out.
// 64-token tiles (one image row segment), fc2_w + dw_w in SMEM.
// Dynamic SMEM: w2 16384 + dws 2304 + gg[64*257]=16448 -> 35136 fl = 140544 B
// ============================================================================
#define FC2_SMEM_FLOATS 35136
__global__ void k_dw_fc2(const float* __restrict__ dww,
                         const float* __restrict__ fc2w, const float* __restrict__ fc2b,
                         float* __restrict__ outp) {
    extern __shared__ float sm[];
    float* w2  = sm;
    float* dws = sm + 16384;
    float* gg  = sm + 16384 + 2304;
    int t = threadIdx.x;
    for (int i = t; i < 16384; i += 256) w2[i]  = fc2w[i];
    for (int i = t; i < 2304;  i += 256) dws[i] = dww[i];
    __syncthreads();

    int tok0 = blockIdx.x * 64;
    int b = tok0 >> 14; int rem = tok0 & 16383; int y = rem >> 7; int x0 = rem & 127;
    const float* fb = g_f + b * NN * HIDN;

    for (int tk = 0; tk < 64; tk++) {
        int xx = x0 + tk;
        float acc = 0.f;
#pragma unroll
        for (int dy = -1; dy <= 1; dy++) {
            int yy = y + dy;
            if ((unsigned)yy < 128u) {
#pragma unroll
                for (int dx = -1; dx <= 1; dx++) {
                    int xc = xx + dx;
                    if ((unsigned)xc < 128u)
                        acc += fb[(yy*128 + xc)*256 + t] * dws[((dy+1)*3 + dx + 1)*256 + t];
                }
            }
        }
        gg[tk*257 + t] = 0.5f * acc * (1.0f + erff(acc * 0.70710678118654752f));
    }
    __syncthreads();

    int ty = t >> 4, tx = t & 15;
    float acc[4][4] = {};
#pragma unroll 2
    for (int ci = 0; ci < 256; ci++) {
        float gv[4], wv[4];
#pragma unroll
        for (int r = 0; r < 4; r++) gv[r] = gg[(ty*4 + r)*257 + ci];
#pragma unroll
        for (int j = 0; j < 4; j++) wv[j] = w2[ci*64 + tx + 16*j];
#pragma unroll
        for (int r = 0; r < 4; r++)
#pragma unroll
            for (int j = 0; j < 4; j++) acc[r][j] += gv[r]*wv[j];
    }
#pragma unroll
    for (int r = 0; r < 4; r++) {
        int tok = tok0 + ty*4 + r;
        int base = tok * 64;
#pragma unroll
        for (int j = 0; j < 4; j++) {
            int jj = tx + 16*j;
            outp[base + jj] = g_x2[base + jj] + acc[r][j] + fc2b[jj];
        }
    }
}

// ============================================================================
extern "C" void kernel_launch(void* const* d_in, const int* in_sizes, int n_in,
                              void* d_out, int out_size) {
    const float* x     = (const float*)d_in[0];
    const float* ln1_g = (const float*)d_in[3];
    const float* ln1_b = (const float*)d_in[4];
    const float* q_w   = (const float*)d_in[5];
    const float* q_b   = (const float*)d_in[6];
    const float* kv_w  = (const float*)d_in[7];
    const float* kv_b  = (const float*)d_in[8];
    const float* proj_w= (const float*)d_in[9];
    const float* proj_b= (const float*)d_in[10];
    const float* sr_w  = (const float*)d_in[11];
    const float* sr_b  = (const float*)d_in[12];
    const float* srn_g = (const float*)d_in[13];
    const float* srn_b = (const float*)d_in[14];
    const float* ln2_g = (const float*)d_in[15];
    const float* ln2_b = (const float*)d_in[16];
    const float* fc1_w = (const float*)d_in[17];
    const float* fc1_b = (const float*)d_in[18];
    const float* dw_w  = (const float*)d_in[19];
    const float* fc2_w = (const float*)d_in[20];
    const float* fc2_b = (const float*)d_in[21];
    float* outp = (float*)d_out;

    cudaFuncSetAttribute(k_attn,    cudaFuncAttributeMaxDynamicSharedMemorySize, ATTN_SMEM_FLOATS*4);
    cudaFuncSetAttribute(k_ln2_fc1, cudaFuncAttributeMaxDynamicSharedMemorySize, FC1_SMEM_FLOATS*4);
    cudaFuncSetAttribute(k_dw_fc2,  cudaFuncAttributeMaxDynamicSharedMemorySize, FC2_SMEM_FLOATS*4);

    k_ln1_q  <<<16384, 256>>>(x, ln1_g, ln1_b, q_w, q_b);
    k_srconv <<<BB*NRR, 256>>>(sr_w, sr_b);
    k_srn_kv <<<BB*NRR/8, 256>>>(srn_g, srn_b, kv_w, kv_b);
    k_attn   <<<dim3(NN/64, BB), 256, ATTN_SMEM_FLOATS*4>>>(x, proj_w, proj_b);
    k_ln2_fc1<<<BB*NN/64, 256, FC1_SMEM_FLOATS*4>>>(ln2_g, ln2_b, fc1_w, fc1_b);
    k_dw_fc2 <<<BB*NN/64, 256, FC2_SMEM_FLOATS*4>>>(dw_w, fc2_w, fc2_b, outp);
}

// round 6
// speedup vs baseline: 2.3120x; 2.3120x over previous
#include <cuda_runtime.h>
#include <math.h>

#define BB   8
#define NN   16384
#define CC   64
#define HIDN 256
#define NRR  256

// ---------------- scratch (device globals; no allocs allowed) ----------------
__device__ float g_h [BB*NN*CC];    // ln1 output
__device__ float g_q [BB*NN*CC];    // q (pre-scaled by 0.125)
__device__ float g_sr[BB*NRR*CC];   // sr conv output
__device__ float g_k [BB*NRR*CC];
__device__ float g_v [BB*NRR*CC];
__device__ float g_x2[BB*NN*CC];    // x + attn-proj residual
__device__ float g_f [BB*NN*HIDN];  // fc1 output (pre dw-conv)

// ============================================================================
// K1: LN1 + q projection. Block = 64 rows. GEMM with LDS.128 operands.
// static smem: qws 16KB + hT 17.4KB
// ============================================================================
__global__ void __launch_bounds__(256, 3)
k_ln1_q(const float* __restrict__ x,
        const float* __restrict__ g1, const float* __restrict__ b1,
        const float* __restrict__ qw, const float* __restrict__ qb) {
    __shared__ __align__(16) float qws[64*64];
    __shared__ __align__(16) float hT[64*68];     // hT[ci][row]
    int t = threadIdx.x;
    for (int i = t; i < 4096; i += 256) qws[i] = qw[i];

    int row = t >> 2, q4 = t & 3;
    int grow = blockIdx.x*64 + row;
    float xv[16]; float s = 0.f, ss = 0.f;
    const float4* xr4 = reinterpret_cast<const float4*>(x + grow*64 + q4*16);
#pragma unroll
    for (int i4 = 0; i4 < 4; i4++) {
        float4 v = xr4[i4];
        xv[i4*4+0]=v.x; xv[i4*4+1]=v.y; xv[i4*4+2]=v.z; xv[i4*4+3]=v.w;
        s += v.x+v.y+v.z+v.w;
        ss += v.x*v.x+v.y*v.y+v.z*v.z+v.w*v.w;
    }
    s  += __shfl_xor_sync(0xffffffffu, s, 1);  s  += __shfl_xor_sync(0xffffffffu, s, 2);
    ss += __shfl_xor_sync(0xffffffffu, ss, 1); ss += __shfl_xor_sync(0xffffffffu, ss, 2);
    float mean = s * (1.0f/64.0f);
    float inv  = rsqrtf(ss * (1.0f/64.0f) - mean*mean + 1e-5f);
    float4* gh4 = reinterpret_cast<float4*>(g_h + grow*64 + q4*16);
#pragma unroll
    for (int i4 = 0; i4 < 4; i4++) {
        float4 hv;
        float* hp = &hv.x;
#pragma unroll
        for (int i = 0; i < 4; i++) {
            int c = q4*16 + i4*4 + i;
            float h = (xv[i4*4+i] - mean) * inv * g1[c] + b1[c];
            hp[i] = h;
            hT[c*68 + row] = h;
        }
        gh4[i4] = hv;
    }
    __syncthreads();

    int ty = t >> 4, tx = t & 15;
    float acc[4][4] = {};
#pragma unroll 8
    for (int ci = 0; ci < 64; ci++) {
        float4 qv = *reinterpret_cast<const float4*>(&hT[ci*68 + ty*4]);
        float4 wv = *reinterpret_cast<const float4*>(&qws[ci*64 + tx*4]);
        const float* qp = &qv.x; const float* wp = &wv.x;
#pragma unroll
        for (int r = 0; r < 4; r++)
#pragma unroll
            for (int j = 0; j < 4; j++) acc[r][j] += qp[r]*wp[j];
    }
    float4 qbv = *reinterpret_cast<const float4*>(qb + tx*4);
    const float* qbp = &qbv.x;
#pragma unroll
    for (int r = 0; r < 4; r++) {
        int gr = blockIdx.x*64 + ty*4 + r;
        float4 o;
        o.x = (acc[r][0]+qbp[0])*0.125f; o.y = (acc[r][1]+qbp[1])*0.125f;
        o.z = (acc[r][2]+qbp[2])*0.125f; o.w = (acc[r][3]+qbp[3])*0.125f;
        *reinterpret_cast<float4*>(g_q + gr*64 + tx*4) = o;
    }
}

// ============================================================================
// K2: spatial-reduction conv (8x8 s8). 4 output positions per block (amortize
// the 1MB weight stream 4x). dyn smem: patch 4*4096 + red 1024 = 69.6KB.
// ============================================================================
__global__ void __launch_bounds__(256, 3)
k_srconv(const float* __restrict__ srw, const float* __restrict__ srb) {
    extern __shared__ float sm[];
    float* patch = sm;            // [4][4096]
    float* red   = sm + 16384;    // [4 part][4 pos][64 c]
    int grp = blockIdx.x;                  // 0..511
    int b = grp >> 6; int p = grp & 63; int oy = p >> 2, ox0 = (p & 3)*4;
    int t = threadIdx.x;
    int c = t & 63, part = t >> 6;
    const float* hb = g_h + (b * NN) * 64;
    for (int i = t; i < 4*4096; i += 256) {
        int pp = i >> 12, rem = i & 4095;
        int ij = rem >> 6, ci = rem & 63; int ii = ij >> 3, j = ij & 7;
        patch[i] = hb[((oy*8 + ii) * 128 + (ox0+pp)*8 + j) * 64 + ci];
    }
    __syncthreads();
    float a0=0.f, a1=0.f, a2=0.f, a3=0.f;
    int k0 = part * 1024;
#pragma unroll 8
    for (int k = k0; k < k0 + 1024; k++) {
        float w = srw[k*64 + c];
        a0 += patch[k]          * w;
        a1 += patch[4096 + k]   * w;
        a2 += patch[8192 + k]   * w;
        a3 += patch[12288 + k]  * w;
    }
    red[part*256 + 0*64 + c] = a0;
    red[part*256 + 1*64 + c] = a1;
    red[part*256 + 2*64 + c] = a2;
    red[part*256 + 3*64 + c] = a3;
    __syncthreads();
    {
        int pp = t >> 6, cc2 = t & 63;
        float r0 = red[0*256 + pp*64 + cc2] + red[1*256 + pp*64 + cc2]
                 + red[2*256 + pp*64 + cc2] + red[3*256 + pp*64 + cc2];
        int pos = b*256 + oy*16 + ox0 + pp;
        g_sr[pos*64 + cc2] = srb[cc2] + r0;
    }
}

// ============================================================================
// K3: LN over sr output + kv projection (64 -> 128). Warp per row. (tiny)
// ============================================================================
__global__ void k_srn_kv(const float* __restrict__ gs, const float* __restrict__ bs,
                         const float* __restrict__ kvw, const float* __restrict__ kvb) {
    __shared__ float ws[64*128];
    __shared__ float rowbuf[8][64];
    int t = threadIdx.x;
    for (int i = t; i < 8192; i += 256) ws[i] = kvw[i];
    __syncthreads();
    int warp = t >> 5, lane = t & 31;
    int r = blockIdx.x * 8 + warp;
    const float* xr = g_sr + r * 64;
    float a0 = xr[lane], a1 = xr[lane + 32];
    float s = a0 + a1;
#pragma unroll
    for (int o = 16; o; o >>= 1) s += __shfl_xor_sync(0xffffffffu, s, o);
    float mean = s * (1.0f/64.0f);
    float d0 = a0 - mean, d1 = a1 - mean;
    float v = d0*d0 + d1*d1;
#pragma unroll
    for (int o = 16; o; o >>= 1) v += __shfl_xor_sync(0xffffffffu, v, o);
    float inv = rsqrtf(v * (1.0f/64.0f) + 1e-5f);
    float h0 = d0 * inv * gs[lane]      + bs[lane];
    float h1 = d1 * inv * gs[lane + 32] + bs[lane + 32];
    rowbuf[warp][lane]      = h0;
    rowbuf[warp][lane + 32] = h1;
    __syncwarp();
    float a  = kvb[lane], bq = kvb[lane+32], cv = kvb[lane+64], dv = kvb[lane+96];
#pragma unroll 8
    for (int ci = 0; ci < 64; ci++) {
        float hv = rowbuf[warp][ci];
        const float* w = ws + ci*128;
        a  += hv * w[lane];
        bq += hv * w[lane+32];
        cv += hv * w[lane+64];
        dv += hv * w[lane+96];
    }
    g_k[r*64 + lane]      = a;
    g_k[r*64 + lane + 32] = bq;
    g_v[r*64 + lane]      = cv;
    g_v[r*64 + lane + 32] = dv;
}

// ============================================================================
// K4: flash attention + out-proj + residual. Block = 64 queries, 4 key-tiles
// of 64 streamed through smem with online softmax; output acc in registers.
// dyn smem floats (pad 68): qsT[0) kTt[4352) vst[8704) psT[13056) = 17408 fl
// epilogue aliases: osT @4352, pw @8704.   69.6KB -> 3 CTAs/SM.
// ============================================================================
#define ATTN_SMEM_FLOATS 17408
__global__ void __launch_bounds__(256, 3)
k_attn(const float* __restrict__ x,
       const float* __restrict__ pwg, const float* __restrict__ pb) {
    extern __shared__ __align__(16) float sm[];
    float* qsT = sm;            // [ci][row]
    float* kTt = sm + 4352;     // [ci][key]
    float* vst = sm + 8704;     // [key][c]
    float* psT = sm + 13056;    // [key][row]
    float* osT = sm + 4352;     // alias kTt
    float* pw  = sm + 8704;     // alias vst

    int t = threadIdx.x;
    int b = blockIdx.y;
    int qtile = blockIdx.x;
    int ty = t >> 4, tx = t & 15;

    // load q tile (transposed) + first k/v tile
    for (int idx = t; idx < 4096; idx += 256) {
        int qq = idx >> 6, c = idx & 63;
        qsT[c*68 + qq] = g_q[(b*NN + qtile*64 + qq)*64 + c];
        kTt[c*68 + qq] = g_k[(b*256 + qq)*64 + c];    // qq as key idx
        vst[qq*68 + c] = g_v[(b*256 + qq)*64 + c];
    }
    __syncthreads();

    float m[4], l[4], o[4][4];
#pragma unroll
    for (int r = 0; r < 4; r++) { m[r] = -1e30f; l[r] = 0.f;
#pragma unroll
        for (int j = 0; j < 4; j++) o[r][j] = 0.f; }

#pragma unroll 1
    for (int kt = 0; kt < 4; kt++) {
        // ---- QK tile: 64q x 64k ----
        float acc[4][4] = {};
#pragma unroll 8
        for (int ci = 0; ci < 64; ci++) {
            float4 qv = *reinterpret_cast<const float4*>(&qsT[ci*68 + ty*4]);
            float4 kv = *reinterpret_cast<const float4*>(&kTt[ci*68 + tx*4]);
            const float* qp = &qv.x; const float* kp = &kv.x;
#pragma unroll
            for (int r = 0; r < 4; r++)
#pragma unroll
                for (int j = 0; j < 4; j++) acc[r][j] += qp[r]*kp[j];
        }
        // ---- online softmax update (rows owned by the 16-thread tx group) ----
#pragma unroll
        for (int r = 0; r < 4; r++) {
            float tmax = fmaxf(fmaxf(acc[r][0], acc[r][1]), fmaxf(acc[r][2], acc[r][3]));
            tmax = fmaxf(tmax, __shfl_xor_sync(0xffffffffu, tmax, 1));
            tmax = fmaxf(tmax, __shfl_xor_sync(0xffffffffu, tmax, 2));
            tmax = fmaxf(tmax, __shfl_xor_sync(0xffffffffu, tmax, 4));
            tmax = fmaxf(tmax, __shfl_xor_sync(0xffffffffu, tmax, 8));
            float newm = fmaxf(m[r], tmax);
            float scale = expf(m[r] - newm);
            float rsum = 0.f;
#pragma unroll
            for (int j = 0; j < 4; j++) {
                float e = expf(acc[r][j] - newm);
                acc[r][j] = e;
                rsum += e;
            }
            rsum += __shfl_xor_sync(0xffffffffu, rsum, 1);
            rsum += __shfl_xor_sync(0xffffffffu, rsum, 2);
            rsum += __shfl_xor_sync(0xffffffffu, rsum, 4);
            rsum += __shfl_xor_sync(0xffffffffu, rsum, 8);
            l[r] = l[r]*scale + rsum;
            m[r] = newm;
#pragma unroll
            for (int j = 0; j < 4; j++) o[r][j] *= scale;
        }
        // store P transposed: psT[key][row], STS.128 over 4 rows
#pragma unroll
        for (int j = 0; j < 4; j++) {
            float4 pv; pv.x = acc[0][j]; pv.y = acc[1][j]; pv.z = acc[2][j]; pv.w = acc[3][j];
            *reinterpret_cast<float4*>(&psT[(tx*4 + j)*68 + ty*4]) = pv;
        }
        __syncthreads();
        // ---- AV tile ----
#pragma unroll 8
        for (int key = 0; key < 64; key++) {
            float4 pv = *reinterpret_cast<const float4*>(&psT[key*68 + ty*4]);
            float4 vv = *reinterpret_cast<const float4*>(&vst[key*68 + tx*4]);
            const float* pp = &pv.x; const float* vp = &vv.x;
#pragma unroll
            for (int r = 0; r < 4; r++)
#pragma unroll
                for (int j = 0; j < 4; j++) o[r][j] += pp[r]*vp[j];
        }
        __syncthreads();
        if (kt < 3) {
            for (int idx = t; idx < 4096; idx += 256) {
                int mm = idx >> 6, c = idx & 63;
                kTt[c*68 + mm] = g_k[(b*256 + (kt+1)*64 + mm)*64 + c];
                vst[mm*68 + c] = g_v[(b*256 + (kt+1)*64 + mm)*64 + c];
            }
            __syncthreads();
        }
    }

    // normalize + stage for projection
#pragma unroll
    for (int r = 0; r < 4; r++) {
        float rinv = 1.0f / l[r];
#pragma unroll
        for (int j = 0; j < 4; j++) o[r][j] *= rinv;
    }
#pragma unroll
    for (int j = 0; j < 4; j++) {
        float4 ov; ov.x = o[0][j]; ov.y = o[1][j]; ov.z = o[2][j]; ov.w = o[3][j];
        *reinterpret_cast<float4*>(&osT[(tx*4 + j)*68 + ty*4]) = ov;
    }
    for (int i = t; i < 4096; i += 256) pw[i] = pwg[i];
    __syncthreads();

    // ---- out projection + residual ----
    float acc[4][4] = {};
#pragma unroll 8
    for (int ci = 0; ci < 64; ci++) {
        float4 ov = *reinterpret_cast<const float4*>(&osT[ci*68 + ty*4]);
        float4 wv = *reinterpret_cast<const float4*>(&pw[ci*64 + tx*4]);
        const float* op = &ov.x; const float* wp = &wv.x;
#pragma unroll
        for (int r = 0; r < 4; r++)
#pragma unroll
            for (int j = 0; j < 4; j++) acc[r][j] += op[r]*wp[j];
    }
    float4 pbv = *reinterpret_cast<const float4*>(pb + tx*4);
#pragma unroll
    for (int r = 0; r < 4; r++) {
        int gi = (b*NN + qtile*64 + ty*4 + r)*64;
        float4 xv = *reinterpret_cast<const float4*>(x + gi + tx*4);
        float4 ov;
        ov.x = xv.x + acc[r][0] + pbv.x;
        ov.y = xv.y + acc[r][1] + pbv.y;
        ov.z = xv.z + acc[r][2] + pbv.z;
        ov.w = xv.w + acc[r][3] + pbv.w;
        *reinterpret_cast<float4*>(g_x2 + gi + tx*4) = ov;
    }
}

// ============================================================================
// K5: LN2 + fc1 (64 -> 256). dyn smem: ws 16384 + h2T 4352 = 82.9KB -> 2 CTAs
// ============================================================================
#define FC1_SMEM_FLOATS 20736
__global__ void __launch_bounds__(256, 2)
k_ln2_fc1(const float* __restrict__ g2, const float* __restrict__ b2,
          const float* __restrict__ fc1w, const float* __restrict__ fc1b) {
    extern __shared__ __align__(16) float sm[];
    float* ws  = sm;            // [ci][cout] 64x256
    float* h2T = sm + 16384;    // [ci][row]  64x68
    int t = threadIdx.x;
    for (int i = t; i < 16384; i += 256) ws[i] = fc1w[i];

    int row = t >> 2, q4 = t & 3;
    int grow = blockIdx.x*64 + row;
    float xv[16]; float s = 0.f, ss = 0.f;
    const float4* xr4 = reinterpret_cast<const float4*>(g_x2 + grow*64 + q4*16);
#pragma unroll
    for (int i4 = 0; i4 < 4; i4++) {
        float4 v = xr4[i4];
        xv[i4*4+0]=v.x; xv[i4*4+1]=v.y; xv[i4*4+2]=v.z; xv[i4*4+3]=v.w;
        s += v.x+v.y+v.z+v.w;
        ss += v.x*v.x+v.y*v.y+v.z*v.z+v.w*v.w;
    }
    s  += __shfl_xor_sync(0xffffffffu, s, 1);  s  += __shfl_xor_sync(0xffffffffu, s, 2);
    ss += __shfl_xor_sync(0xffffffffu, ss, 1); ss += __shfl_xor_sync(0xffffffffu, ss, 2);
    float mean = s * (1.0f/64.0f);
    float inv  = rsqrtf(ss * (1.0f/64.0f) - mean*mean + 1e-5f);
#pragma unroll
    for (int i = 0; i < 16; i++) {
        int c = q4*16 + i;
        h2T[c*68 + row] = (xv[i] - mean) * inv * g2[c] + b2[c];
    }
    __syncthreads();

    int ty = t >> 4, tx = t & 15;
#pragma unroll
    for (int pass = 0; pass < 4; pass++) {
        int j0 = pass * 64;
        float acc[4][4] = {};
#pragma unroll 8
        for (int ci = 0; ci < 64; ci++) {
            float4 hv = *reinterpret_cast<const float4*>(&h2T[ci*68 + ty*4]);
            float4 wv = *reinterpret_cast<const float4*>(&ws[ci*256 + j0 + tx*4]);
            const float* hp = &hv.x; const float* wp = &wv.x;
#pragma unroll
            for (int r = 0; r < 4; r++)
#pragma unroll
                for (int j = 0; j < 4; j++) acc[r][j] += hp[r]*wp[j];
        }
        float4 bv = *reinterpret_cast<const float4*>(fc1b + j0 + tx*4);
#pragma unroll
        for (int r = 0; r < 4; r++) {
            int gr = blockIdx.x*64 + ty*4 + r;
            float4 ov;
            ov.x = acc[r][0]+bv.x; ov.y = acc[r][1]+bv.y;
            ov.z = acc[r][2]+bv.z; ov.w = acc[r][3]+bv.w;
            *reinterpret_cast<float4*>(g_f + gr*256 + j0 + tx*4) = ov;
        }
    }
}

// ============================================================================
// K6: depthwise 3x3 SAME + GELU + fc2 (256->64) + residual. 64-token tiles.
// Rolling column-dot dw conv (3 loads/col instead of 9/token). Channels split
// into 2 chunks of 128 so the GELU buffer is half-size.
// dyn smem: w2 16384 + dws 2304 + ggT 128*68=8704 -> 27392 fl = 109.6KB -> 2 CTAs
// ============================================================================
#define FC2_SMEM_FLOATS 27392
__global__ void __launch_bounds__(256, 2)
k_dw_fc2(const float* __restrict__ dww,
         const float* __restrict__ fc2w, const float* __restrict__ fc2b,
         float* __restrict__ outp) {
    extern __shared__ __align__(16) float sm[];
    float* w2  = sm;            // [ci][cout] 256x64
    float* dws = sm + 16384;    // 9x256
    float* ggT = sm + 18688;    // [ci_local][tok] 128x68
    int t = threadIdx.x;
    for (int i = t; i < 16384; i += 256) w2[i]  = fc2w[i];
    for (int i = t; i < 2304;  i += 256) dws[i] = dww[i];
    __syncthreads();

    int tok0 = blockIdx.x * 64;
    int b = tok0 >> 14; int rem = tok0 & 16383; int y = rem >> 7; int x0 = rem & 127;
    const float* fb = g_f + b * NN * HIDN;
    int ty = t >> 4, tx = t & 15;

    float acc[4][4] = {};
#pragma unroll 1
    for (int chunk = 0; chunk < 2; chunk++) {
        int ch0 = chunk * 128;
        // ---- depthwise conv (rolling) + GELU ----
        {
            int ci = (t & 127) + ch0;
            int th = t >> 7;                 // token half: 32 tokens each
            int tstart = x0 + th*32;
            float w00 = dws[0*256+ci], w01 = dws[1*256+ci], w02 = dws[2*256+ci];
            float w10 = dws[3*256+ci], w11 = dws[4*256+ci], w12 = dws[5*256+ci];
            float w20 = dws[6*256+ci], w21 = dws[7*256+ci], w22 = dws[8*256+ci];
            bool y0ok = (y > 0), y2ok = (y < 127);
            float A = 0.f, Bc = 0.f, Cn = 0.f;
            const float* fr0 = fb + ((y-1)*128)*256 + ci;
            const float* fr1 = fb + ( y   *128)*256 + ci;
            const float* fr2 = fb + ((y+1)*128)*256 + ci;
#pragma unroll 2
            for (int c = tstart-1; c <= tstart+32; c++) {
                float a0 = 0.f, a1 = 0.f, a2 = 0.f;
                if ((unsigned)c < 128u) {
                    float f0 = y0ok ? fr0[c*256] : 0.f;
                    float f1 = fr1[c*256];
                    float f2 = y2ok ? fr2[c*256] : 0.f;
                    a0 = f0*w00 + f1*w10 + f2*w20;
                    a1 = f0*w01 + f1*w11 + f2*w21;
                    a2 = f0*w02 + f1*w12 + f2*w22;
                }
                A += a2; Bc += a1; Cn += a0;
                int xo = c - 1;
                if (xo >= tstart && xo < tstart + 32) {
                    float v = A;
                    float g = 0.5f * v * (1.0f + erff(v * 0.70710678118654752f));
                    ggT[(ci - ch0)*68 + (xo - x0)] = g;
                }
                A = Bc; Bc = Cn; Cn = 0.f;
            }
        }
        __syncthreads();
        // ---- fc2 partial over this channel chunk ----
#pragma unroll 8
        for (int ci = 0; ci < 128; ci++) {
            float4 gv = *reinterpret_cast<const float4*>(&ggT[ci*68 + ty*4]);
            float4 wv = *reinterpret_cast<const float4*>(&w2[(ch0+ci)*64 + tx*4]);
            const float* gp = &gv.x; const float* wp = &wv.x;
#pragma unroll
            for (int r = 0; r < 4; r++)
#pragma unroll
                for (int j = 0; j < 4; j++) acc[r][j] += gp[r]*wp[j];
        }
        __syncthreads();
    }

    float4 bv = *reinterpret_cast<const float4*>(fc2b + tx*4);
#pragma unroll
    for (int r = 0; r < 4; r++) {
        int base = (tok0 + ty*4 + r) * 64;
        float4 xv = *reinterpret_cast<const float4*>(g_x2 + base + tx*4);
        float4 ov;
        ov.x = xv.x + acc[r][0] + bv.x;
        ov.y = xv.y + acc[r][1] + bv.y;
        ov.z = xv.z + acc[r][2] + bv.z;
        ov.w = xv.w + acc[r][3] + bv.w;
        *reinterpret_cast<float4*>(outp + base + tx*4) = ov;
    }
}

// ============================================================================
extern "C" void kernel_launch(void* const* d_in, const int* in_sizes, int n_in,
                              void* d_out, int out_size) {
    const float* x     = (const float*)d_in[0];
    const float* ln1_g = (const float*)d_in[3];
    const float* ln1_b = (const float*)d_in[4];
    const float* q_w   = (const float*)d_in[5];
    const float* q_b   = (const float*)d_in[6];
    const float* kv_w  = (const float*)d_in[7];
    const float* kv_b  = (const float*)d_in[8];
    const float* proj_w= (const float*)d_in[9];
    const float* proj_b= (const float*)d_in[10];
    const float* sr_w  = (const float*)d_in[11];
    const float* sr_b  = (const float*)d_in[12];
    const float* srn_g = (const float*)d_in[13];
    const float* srn_b = (const float*)d_in[14];
    const float* ln2_g = (const float*)d_in[15];
    const float* ln2_b = (const float*)d_in[16];
    const float* fc1_w = (const float*)d_in[17];
    const float* fc1_b = (const float*)d_in[18];
    const float* dw_w  = (const float*)d_in[19];
    const float* fc2_w = (const float*)d_in[20];
    const float* fc2_b = (const float*)d_in[21];
    float* outp = (float*)d_out;

    cudaFuncSetAttribute(k_srconv,  cudaFuncAttributeMaxDynamicSharedMemorySize, (16384+1024)*4);
    cudaFuncSetAttribute(k_attn,    cudaFuncAttributeMaxDynamicSharedMemorySize, ATTN_SMEM_FLOATS*4);
    cudaFuncSetAttribute(k_ln2_fc1, cudaFuncAttributeMaxDynamicSharedMemorySize, FC1_SMEM_FLOATS*4);
    cudaFuncSetAttribute(k_dw_fc2,  cudaFuncAttributeMaxDynamicSharedMemorySize, FC2_SMEM_FLOATS*4);

    k_ln1_q  <<<BB*NN/64, 256>>>(x, ln1_g, ln1_b, q_w, q_b);
    k_srconv <<<BB*NRR/4, 256, (16384+1024)*4>>>(sr_w, sr_b);
    k_srn_kv <<<BB*NRR/8, 256>>>(srn_g, srn_b, kv_w, kv_b);
    k_attn   <<<dim3(NN/64, BB), 256, ATTN_SMEM_FLOATS*4>>>(x, proj_w, proj_b);
    k_ln2_fc1<<<BB*NN/64, 256, FC1_SMEM_FLOATS*4>>>(ln2_g, ln2_b, fc1_w, fc1_b);
    k_dw_fc2 <<<BB*NN/64, 256, FC2_SMEM_FLOATS*4>>>(dw_w, fc2_w, fc2_b, outp);
}

// round 7
// speedup vs baseline: 4.0383x; 1.7466x over previous
#include <cuda_runtime.h>
#include <cuda_bf16.h>
#include <math.h>

#define BB   8
#define NN   16384
#define CC   64
#define HIDN 256
#define NRR  256

// ---------------- scratch (device globals; no allocs allowed) ----------------
__device__ float g_h [BB*NN*CC];    // ln1 output
__device__ float g_q [BB*NN*CC];    // q (pre-scaled by 0.125)
__device__ float g_sr[BB*NRR*CC];   // sr conv output
__device__ float g_k [BB*NRR*CC];
__device__ float g_v [BB*NRR*CC];
__device__ float g_x2[BB*NN*CC];    // x + attn-proj residual
__device__ float g_f [BB*NN*HIDN];  // fc1 output (pre dw-conv)

// ---------------- mma helpers ----------------
__device__ __forceinline__ void mma16816(float* c, const unsigned* a, unsigned b0, unsigned b1) {
    asm volatile("mma.sync.aligned.m16n8k16.row.col.f32.bf16.bf16.f32 "
        "{%0,%1,%2,%3}, {%4,%5,%6,%7}, {%8,%9}, {%0,%1,%2,%3};"
        : "+f"(c[0]), "+f"(c[1]), "+f"(c[2]), "+f"(c[3])
        : "r"(a[0]), "r"(a[1]), "r"(a[2]), "r"(a[3]), "r"(b0), "r"(b1));
}
__device__ __forceinline__ unsigned packbf(float lo, float hi) {
    unsigned r; asm("cvt.rn.bf16x2.f32 %0, %1, %2;" : "=r"(r) : "f"(hi), "f"(lo));
    return r;
}

// ============================================================================
// K1: LN1 + q projection. Block = 64 rows. Scalar GEMM with LDS.128 operands.
// ============================================================================
__global__ void __launch_bounds__(256, 3)
k_ln1_q(const float* __restrict__ x,
        const float* __restrict__ g1, const float* __restrict__ b1,
        const float* __restrict__ qw, const float* __restrict__ qb) {
    __shared__ __align__(16) float qws[64*64];
    __shared__ __align__(16) float hT[64*68];     // hT[ci][row]
    int t = threadIdx.x;
    for (int i = t; i < 4096; i += 256) qws[i] = qw[i];

    int row = t >> 2, q4 = t & 3;
    int grow = blockIdx.x*64 + row;
    float xv[16]; float s = 0.f, ss = 0.f;
    const float4* xr4 = reinterpret_cast<const float4*>(x + grow*64 + q4*16);
#pragma unroll
    for (int i4 = 0; i4 < 4; i4++) {
        float4 v = xr4[i4];
        xv[i4*4+0]=v.x; xv[i4*4+1]=v.y; xv[i4*4+2]=v.z; xv[i4*4+3]=v.w;
        s += v.x+v.y+v.z+v.w;
        ss += v.x*v.x+v.y*v.y+v.z*v.z+v.w*v.w;
    }
    s  += __shfl_xor_sync(0xffffffffu, s, 1);  s  += __shfl_xor_sync(0xffffffffu, s, 2);
    ss += __shfl_xor_sync(0xffffffffu, ss, 1); ss += __shfl_xor_sync(0xffffffffu, ss, 2);
    float mean = s * (1.0f/64.0f);
    float inv  = rsqrtf(ss * (1.0f/64.0f) - mean*mean + 1e-5f);
    float4* gh4 = reinterpret_cast<float4*>(g_h + grow*64 + q4*16);
#pragma unroll
    for (int i4 = 0; i4 < 4; i4++) {
        float4 hv;
        float* hp = &hv.x;
#pragma unroll
        for (int i = 0; i < 4; i++) {
            int c = q4*16 + i4*4 + i;
            float h = (xv[i4*4+i] - mean) * inv * g1[c] + b1[c];
            hp[i] = h;
            hT[c*68 + row] = h;
        }
        gh4[i4] = hv;
    }
    __syncthreads();

    int ty = t >> 4, tx = t & 15;
    float acc[4][4] = {};
#pragma unroll 8
    for (int ci = 0; ci < 64; ci++) {
        float4 qv = *reinterpret_cast<const float4*>(&hT[ci*68 + ty*4]);
        float4 wv = *reinterpret_cast<const float4*>(&qws[ci*64 + tx*4]);
        const float* qp = &qv.x; const float* wp = &wv.x;
#pragma unroll
        for (int r = 0; r < 4; r++)
#pragma unroll
            for (int j = 0; j < 4; j++) acc[r][j] += qp[r]*wp[j];
    }
    float4 qbv = *reinterpret_cast<const float4*>(qb + tx*4);
    const float* qbp = &qbv.x;
#pragma unroll
    for (int r = 0; r < 4; r++) {
        int gr = blockIdx.x*64 + ty*4 + r;
        float4 o;
        o.x = (acc[r][0]+qbp[0])*0.125f; o.y = (acc[r][1]+qbp[1])*0.125f;
        o.z = (acc[r][2]+qbp[2])*0.125f; o.w = (acc[r][3]+qbp[3])*0.125f;
        *reinterpret_cast<float4*>(g_q + gr*64 + tx*4) = o;
    }
}

// ============================================================================
// K2: spatial-reduction conv (8x8 s8). 4 output positions per block.
// ============================================================================
__global__ void __launch_bounds__(256, 3)
k_srconv(const float* __restrict__ srw, const float* __restrict__ srb) {
    extern __shared__ float sm[];
    float* patch = sm;            // [4][4096]
    float* red   = sm + 16384;    // [4 part][4 pos][64 c]
    int grp = blockIdx.x;                  // 0..511
    int b = grp >> 6; int p = grp & 63; int oy = p >> 2, ox0 = (p & 3)*4;
    int t = threadIdx.x;
    int c = t & 63, part = t >> 6;
    const float* hb = g_h + (b * NN) * 64;
    for (int i = t; i < 4*4096; i += 256) {
        int pp = i >> 12, rem = i & 4095;
        int ij = rem >> 6, ci = rem & 63; int ii = ij >> 3, j = ij & 7;
        patch[i] = hb[((oy*8 + ii) * 128 + (ox0+pp)*8 + j) * 64 + ci];
    }
    __syncthreads();
    float a0=0.f, a1=0.f, a2=0.f, a3=0.f;
    int k0 = part * 1024;
#pragma unroll 8
    for (int k = k0; k < k0 + 1024; k++) {
        float w = srw[k*64 + c];
        a0 += patch[k]          * w;
        a1 += patch[4096 + k]   * w;
        a2 += patch[8192 + k]   * w;
        a3 += patch[12288 + k]  * w;
    }
    red[part*256 + 0*64 + c] = a0;
    red[part*256 + 1*64 + c] = a1;
    red[part*256 + 2*64 + c] = a2;
    red[part*256 + 3*64 + c] = a3;
    __syncthreads();
    {
        int pp = t >> 6, cc2 = t & 63;
        float r0 = red[0*256 + pp*64 + cc2] + red[1*256 + pp*64 + cc2]
                 + red[2*256 + pp*64 + cc2] + red[3*256 + pp*64 + cc2];
        int pos = b*256 + oy*16 + ox0 + pp;
        g_sr[pos*64 + cc2] = srb[cc2] + r0;
    }
}

// ============================================================================
// K3: LN over sr output + kv projection (64 -> 128). Warp per row. (tiny)
// ============================================================================
__global__ void k_srn_kv(const float* __restrict__ gs, const float* __restrict__ bs,
                         const float* __restrict__ kvw, const float* __restrict__ kvb) {
    __shared__ float ws[64*128];
    __shared__ float rowbuf[8][64];
    int t = threadIdx.x;
    for (int i = t; i < 8192; i += 256) ws[i] = kvw[i];
    __syncthreads();
    int warp = t >> 5, lane = t & 31;
    int r = blockIdx.x * 8 + warp;
    const float* xr = g_sr + r * 64;
    float a0 = xr[lane], a1 = xr[lane + 32];
    float s = a0 + a1;
#pragma unroll
    for (int o = 16; o; o >>= 1) s += __shfl_xor_sync(0xffffffffu, s, o);
    float mean = s * (1.0f/64.0f);
    float d0 = a0 - mean, d1 = a1 - mean;
    float v = d0*d0 + d1*d1;
#pragma unroll
    for (int o = 16; o; o >>= 1) v += __shfl_xor_sync(0xffffffffu, v, o);
    float inv = rsqrtf(v * (1.0f/64.0f) + 1e-5f);
    float h0 = d0 * inv * gs[lane]      + bs[lane];
    float h1 = d1 * inv * gs[lane + 32] + bs[lane + 32];
    rowbuf[warp][lane]      = h0;
    rowbuf[warp][lane + 32] = h1;
    __syncwarp();
    float a  = kvb[lane], bq = kvb[lane+32], cv = kvb[lane+64], dv = kvb[lane+96];
#pragma unroll 8
    for (int ci = 0; ci < 64; ci++) {
        float hv = rowbuf[warp][ci];
        const float* w = ws + ci*128;
        a  += hv * w[lane];
        bq += hv * w[lane+32];
        cv += hv * w[lane+64];
        dv += hv * w[lane+96];
    }
    g_k[r*64 + lane]      = a;
    g_k[r*64 + lane + 32] = bq;
    g_v[r*64 + lane]      = cv;
    g_v[r*64 + lane + 32] = dv;
}

// ============================================================================
// K4: flash attention (bf16 mma.sync) + out-proj + residual.
// Block = 128 threads (4 warps); warp owns 16 q-rows over full 64-key tiles.
// Online softmax entirely warp-local; S C-frags convert directly to P A-frags.
// smem bf16 (pad 72): sq[64x72], sk[64x72], svT[64x72], swT[64x72] = 36.9KB
// ============================================================================
#define APAD 72
#define ATTN_SMEM_BYTES (4*4608*2)
__global__ void __launch_bounds__(128)
k_attn(const float* __restrict__ x,
       const float* __restrict__ pwg, const float* __restrict__ pb) {
    extern __shared__ __align__(16) __nv_bfloat16 smA[];
    __nv_bfloat16* sq  = smA;              // [row][c]
    __nv_bfloat16* sk  = smA + 4608;       // [key][c]
    __nv_bfloat16* svT = smA + 9216;       // [c][key]
    __nv_bfloat16* swT = smA + 13824;      // [cout][cin]

    int t = threadIdx.x;
    int b = blockIdx.y, qtile = blockIdx.x;
    int w = t >> 5, lane = t & 31;
    int g = lane >> 2, tt = lane & 3;
    int m0 = w * 16;

    const float* qg = g_q + (b*NN + (size_t)qtile*64)*64;
    for (int idx = t; idx < 4096; idx += 128) {
        int row = idx >> 6, c = idx & 63;
        sq[row*APAD + c]  = __float2bfloat16_rn(qg[idx]);
        swT[c*APAD + row] = __float2bfloat16_rn(pwg[row*64 + c]); // [cout][cin]
    }
    __syncthreads();

    // Q A-fragments (persist whole kernel)
    unsigned qa[4][4];
#pragma unroll
    for (int kc = 0; kc < 4; kc++) {
        qa[kc][0] = *(const unsigned*)&sq[(m0+g)*APAD   + kc*16 + 2*tt];
        qa[kc][1] = *(const unsigned*)&sq[(m0+g+8)*APAD + kc*16 + 2*tt];
        qa[kc][2] = *(const unsigned*)&sq[(m0+g)*APAD   + kc*16 + 8 + 2*tt];
        qa[kc][3] = *(const unsigned*)&sq[(m0+g+8)*APAD + kc*16 + 8 + 2*tt];
    }

    float mrow[2] = {-1e30f, -1e30f}, lrow[2] = {0.f, 0.f};
    float of[8][4] = {};

#pragma unroll 1
    for (int kt = 0; kt < 4; kt++) {
        const float* kg = g_k + (b*256 + kt*64)*64;
        const float* vg = g_v + (b*256 + kt*64)*64;
        for (int idx = t; idx < 4096; idx += 128) {
            int row = idx >> 6, c = idx & 63;
            sk[row*APAD + c]  = __float2bfloat16_rn(kg[idx]);
            svT[c*APAD + row] = __float2bfloat16_rn(vg[idx]);
        }
        __syncthreads();

        // S = Q K^T  (16 x 64 per warp)
        float sf[8][4] = {};
#pragma unroll
        for (int n = 0; n < 8; n++) {
#pragma unroll
            for (int kc = 0; kc < 4; kc++) {
                unsigned b0 = *(const unsigned*)&sk[(n*8+g)*APAD + kc*16 + 2*tt];
                unsigned b1 = *(const unsigned*)&sk[(n*8+g)*APAD + kc*16 + 8 + 2*tt];
                mma16816(sf[n], qa[kc], b0, b1);
            }
        }
        // online softmax (rows g and g+8)
#pragma unroll
        for (int h = 0; h < 2; h++) {
            float tmax = -1e30f;
#pragma unroll
            for (int n = 0; n < 8; n++)
                tmax = fmaxf(tmax, fmaxf(sf[n][2*h], sf[n][2*h+1]));
            tmax = fmaxf(tmax, __shfl_xor_sync(0xffffffffu, tmax, 1));
            tmax = fmaxf(tmax, __shfl_xor_sync(0xffffffffu, tmax, 2));
            float newm = fmaxf(mrow[h], tmax);
            float scale = __expf(mrow[h] - newm);
            float sum = 0.f;
#pragma unroll
            for (int n = 0; n < 8; n++) {
                float e0 = __expf(sf[n][2*h]   - newm);
                float e1 = __expf(sf[n][2*h+1] - newm);
                sf[n][2*h] = e0; sf[n][2*h+1] = e1;
                sum += e0 + e1;
            }
            sum += __shfl_xor_sync(0xffffffffu, sum, 1);
            sum += __shfl_xor_sync(0xffffffffu, sum, 2);
            lrow[h] = lrow[h]*scale + sum;
            mrow[h] = newm;
#pragma unroll
            for (int n = 0; n < 8; n++) { of[n][2*h] *= scale; of[n][2*h+1] *= scale; }
        }
        // C-frag -> A-frag conversion (register-level, no smem round trip)
        unsigned pa[4][4];
#pragma unroll
        for (int kc = 0; kc < 4; kc++) {
            pa[kc][0] = packbf(sf[2*kc][0],   sf[2*kc][1]);
            pa[kc][1] = packbf(sf[2*kc][2],   sf[2*kc][3]);
            pa[kc][2] = packbf(sf[2*kc+1][0], sf[2*kc+1][1]);
            pa[kc][3] = packbf(sf[2*kc+1][2], sf[2*kc+1][3]);
        }
        // O += P V
#pragma unroll
        for (int n = 0; n < 8; n++) {
#pragma unroll
            for (int kc = 0; kc < 4; kc++) {
                unsigned b0 = *(const unsigned*)&svT[(n*8+g)*APAD + kc*16 + 2*tt];
                unsigned b1 = *(const unsigned*)&svT[(n*8+g)*APAD + kc*16 + 8 + 2*tt];
                mma16816(of[n], pa[kc], b0, b1);
            }
        }
        __syncthreads();
    }

    // normalize + out-projection (bf16 mma) + residual
    float rinv0 = 1.0f/lrow[0], rinv1 = 1.0f/lrow[1];
    unsigned oa[4][4];
#pragma unroll
    for (int kc = 0; kc < 4; kc++) {
        oa[kc][0] = packbf(of[2*kc][0]*rinv0,   of[2*kc][1]*rinv0);
        oa[kc][1] = packbf(of[2*kc][2]*rinv1,   of[2*kc][3]*rinv1);
        oa[kc][2] = packbf(of[2*kc+1][0]*rinv0, of[2*kc+1][1]*rinv0);
        oa[kc][3] = packbf(of[2*kc+1][2]*rinv1, of[2*kc+1][3]*rinv1);
    }
    float rf[8][4] = {};
#pragma unroll
    for (int n = 0; n < 8; n++) {
#pragma unroll
        for (int kc = 0; kc < 4; kc++) {
            unsigned b0 = *(const unsigned*)&swT[(n*8+g)*APAD + kc*16 + 2*tt];
            unsigned b1 = *(const unsigned*)&swT[(n*8+g)*APAD + kc*16 + 8 + 2*tt];
            mma16816(rf[n], oa[kc], b0, b1);
        }
    }
    int row0 = qtile*64 + m0 + g;
#pragma unroll
    for (int n = 0; n < 8; n++) {
        int col = n*8 + 2*tt;
        float2 pbv = *(const float2*)(pb + col);
        size_t gi0 = ((size_t)b*NN + row0)*64 + col;
        float2 xv0 = *(const float2*)(x + gi0);
        float2 o0; o0.x = xv0.x + rf[n][0] + pbv.x; o0.y = xv0.y + rf[n][1] + pbv.y;
        *(float2*)(g_x2 + gi0) = o0;
        size_t gi1 = gi0 + 8*64;
        float2 xv1 = *(const float2*)(x + gi1);
        float2 o1; o1.x = xv1.x + rf[n][2] + pbv.x; o1.y = xv1.y + rf[n][3] + pbv.y;
        *(float2*)(g_x2 + gi1) = o1;
    }
}

// ============================================================================
// K5: LN2 (fp32) + fc1 GEMM 64x256x64 via bf16 mma. 256 threads / 8 warps:
// warp = (mt = w&3 -> 16 rows, nh = w>>2 -> 128 cols).
// smem: h2 [64][72] bf16 + w1T [256][72] bf16 = 46.1KB
// ============================================================================
#define FPAD 72
#define FC1_SMEM_BYTES ((4608 + 256*FPAD)*2)
__global__ void __launch_bounds__(256)
k_ln2_fc1(const float* __restrict__ g2, const float* __restrict__ b2,
          const float* __restrict__ fc1w, const float* __restrict__ fc1b) {
    extern __shared__ __align__(16) __nv_bfloat16 smB[];
    __nv_bfloat16* h2  = smB;           // [row][c]
    __nv_bfloat16* w1T = smB + 4608;    // [cout][cin]
    int t = threadIdx.x;
    for (int idx = t; idx < 16384; idx += 256) {
        int co = idx & 255, ci = idx >> 8;
        w1T[co*FPAD + ci] = __float2bfloat16_rn(fc1w[ci*256 + co]);
    }

    int row = t >> 2, q4 = t & 3;
    int grow = blockIdx.x*64 + row;
    float xv[16]; float s = 0.f, ss = 0.f;
    const float4* xr4 = reinterpret_cast<const float4*>(g_x2 + (size_t)grow*64 + q4*16);
#pragma unroll
    for (int i4 = 0; i4 < 4; i4++) {
        float4 v = xr4[i4];
        xv[i4*4+0]=v.x; xv[i4*4+1]=v.y; xv[i4*4+2]=v.z; xv[i4*4+3]=v.w;
        s += v.x+v.y+v.z+v.w;
        ss += v.x*v.x+v.y*v.y+v.z*v.z+v.w*v.w;
    }
    s  += __shfl_xor_sync(0xffffffffu, s, 1);  s  += __shfl_xor_sync(0xffffffffu, s, 2);
    ss += __shfl_xor_sync(0xffffffffu, ss, 1); ss += __shfl_xor_sync(0xffffffffu, ss, 2);
    float mean = s * (1.0f/64.0f);
    float inv  = rsqrtf(ss * (1.0f/64.0f) - mean*mean + 1e-5f);
#pragma unroll
    for (int i = 0; i < 16; i++) {
        int c = q4*16 + i;
        h2[row*FPAD + c] = __float2bfloat16_rn((xv[i] - mean) * inv * g2[c] + b2[c]);
    }
    __syncthreads();

    int w = t >> 5, lane = t & 31;
    int g = lane >> 2, tt = lane & 3;
    int m0 = (w & 3) * 16, nbase = (w >> 2) * 128;

    unsigned qa[4][4];
#pragma unroll
    for (int kc = 0; kc < 4; kc++) {
        qa[kc][0] = *(const unsigned*)&h2[(m0+g)*FPAD   + kc*16 + 2*tt];
        qa[kc][1] = *(const unsigned*)&h2[(m0+g+8)*FPAD + kc*16 + 2*tt];
        qa[kc][2] = *(const unsigned*)&h2[(m0+g)*FPAD   + kc*16 + 8 + 2*tt];
        qa[kc][3] = *(const unsigned*)&h2[(m0+g+8)*FPAD + kc*16 + 8 + 2*tt];
    }
    float of[16][4] = {};
#pragma unroll
    for (int n = 0; n < 16; n++) {
        int ncol = nbase + n*8;
#pragma unroll
        for (int kc = 0; kc < 4; kc++) {
            unsigned b0 = *(const unsigned*)&w1T[(ncol+g)*FPAD + kc*16 + 2*tt];
            unsigned b1 = *(const unsigned*)&w1T[(ncol+g)*FPAD + kc*16 + 8 + 2*tt];
            mma16816(of[n], qa[kc], b0, b1);
        }
    }
    int grow0 = blockIdx.x*64 + m0 + g;
#pragma unroll
    for (int n = 0; n < 16; n++) {
        int col = nbase + n*8 + 2*tt;
        float2 bv = *(const float2*)(fc1b + col);
        size_t gi0 = (size_t)grow0*256 + col;
        float2 o0; o0.x = of[n][0] + bv.x; o0.y = of[n][1] + bv.y;
        *(float2*)(g_f + gi0) = o0;
        float2 o1; o1.x = of[n][2] + bv.x; o1.y = of[n][3] + bv.y;
        *(float2*)(g_f + gi0 + 8*256) = o1;
    }
}

// ============================================================================
// K6: depthwise 3x3 SAME (fp32 rolling) + exact GELU -> bf16, then fc2 GEMM
// 64x64x256 via bf16 mma + residual.
// smem: dws 9216B f32, w2T [64][264] bf16 33792B, gg [64][264] bf16 33792B = 76.8KB
// ============================================================================
#define GPAD 264
#define FC2_SMEM_BYTES (9216 + 64*GPAD*2*2)
__global__ void __launch_bounds__(256)
k_dw_fc2(const float* __restrict__ dww,
         const float* __restrict__ fc2w, const float* __restrict__ fc2b,
         float* __restrict__ outp) {
    extern __shared__ __align__(16) char smC[];
    float* dws = (float*)smC;                                    // [9][256]
    __nv_bfloat16* w2T = (__nv_bfloat16*)(smC + 9216);           // [cout][cin]
    __nv_bfloat16* gg  = (__nv_bfloat16*)(smC + 9216 + 64*GPAD*2); // [tok][ci]
    int t = threadIdx.x;
    for (int i = t; i < 2304; i += 256) dws[i] = dww[i];
    for (int idx = t; idx < 16384; idx += 256) {
        int co = idx & 63, ci = idx >> 6;
        w2T[co*GPAD + ci] = __float2bfloat16_rn(fc2w[ci*64 + co]);
    }
    __syncthreads();

    int tok0 = blockIdx.x * 64;
    int b = tok0 >> 14; int rem = tok0 & 16383; int y = rem >> 7; int x0 = rem & 127;
    const float* fb = g_f + (size_t)b * NN * HIDN;

    // ---- depthwise conv (rolling column dots) + GELU, t = channel ----
    {
        int ci = t;
        float w00 = dws[0*256+ci], w01 = dws[1*256+ci], w02 = dws[2*256+ci];
        float w10 = dws[3*256+ci], w11 = dws[4*256+ci], w12 = dws[5*256+ci];
        float w20 = dws[6*256+ci], w21 = dws[7*256+ci], w22 = dws[8*256+ci];
        bool y0ok = (y > 0), y2ok = (y < 127);
        float A = 0.f, Bc = 0.f, Cn = 0.f;
        const float* fr0 = fb + ((size_t)(y-1)*128)*256 + ci;
        const float* fr1 = fb + ((size_t) y   *128)*256 + ci;
        const float* fr2 = fb + ((size_t)(y+1)*128)*256 + ci;
#pragma unroll 4
        for (int c = x0-1; c <= x0+64; c++) {
            float a0 = 0.f, a1 = 0.f, a2 = 0.f;
            if ((unsigned)c < 128u) {
                float f0 = y0ok ? fr0[(size_t)c*256] : 0.f;
                float f1 = fr1[(size_t)c*256];
                float f2 = y2ok ? fr2[(size_t)c*256] : 0.f;
                a0 = f0*w00 + f1*w10 + f2*w20;
                a1 = f0*w01 + f1*w11 + f2*w21;
                a2 = f0*w02 + f1*w12 + f2*w22;
            }
            A += a2; Bc += a1; Cn += a0;
            int xo = c - 1;
            if (xo >= x0 && xo < x0 + 64) {
                float v = A;
                float ge = 0.5f * v * (1.0f + erff(v * 0.70710678118654752f));
                gg[(xo - x0)*GPAD + ci] = __float2bfloat16_rn(ge);
            }
            A = Bc; Bc = Cn; Cn = 0.f;
        }
    }
    __syncthreads();

    // ---- fc2 GEMM via mma: warp = (mt = w&3, nh = w>>2 -> 32 cols) ----
    int w = t >> 5, lane = t & 31;
    int g = lane >> 2, tt = lane & 3;
    int m0 = (w & 3) * 16, nbase = (w >> 2) * 32;
    float of[4][4] = {};
#pragma unroll
    for (int kc = 0; kc < 16; kc++) {
        unsigned aa[4];
        aa[0] = *(const unsigned*)&gg[(m0+g)*GPAD   + kc*16 + 2*tt];
        aa[1] = *(const unsigned*)&gg[(m0+g+8)*GPAD + kc*16 + 2*tt];
        aa[2] = *(const unsigned*)&gg[(m0+g)*GPAD   + kc*16 + 8 + 2*tt];
        aa[3] = *(const unsigned*)&gg[(m0+g+8)*GPAD + kc*16 + 8 + 2*tt];
#pragma unroll
        for (int n = 0; n < 4; n++) {
            int ncol = nbase + n*8;
            unsigned b0 = *(const unsigned*)&w2T[(ncol+g)*GPAD + kc*16 + 2*tt];
            unsigned b1 = *(const unsigned*)&w2T[(ncol+g)*GPAD + kc*16 + 8 + 2*tt];
            mma16816(of[n], aa, b0, b1);
        }
    }
    int tok = tok0 + m0 + g;
#pragma unroll
    for (int n = 0; n < 4; n++) {
        int col = nbase + n*8 + 2*tt;
        float2 bv = *(const float2*)(fc2b + col);
        size_t gi0 = (size_t)tok*64 + col;
        float2 xv0 = *(const float2*)(g_x2 + gi0);
        float2 o0; o0.x = xv0.x + of[n][0] + bv.x; o0.y = xv0.y + of[n][1] + bv.y;
        *(float2*)(outp + gi0) = o0;
        size_t gi1 = gi0 + 8*64;
        float2 xv1 = *(const float2*)(g_x2 + gi1);
        float2 o1; o1.x = xv1.x + of[n][2] + bv.x; o1.y = xv1.y + of[n][3] + bv.y;
        *(float2*)(outp + gi1) = o1;
    }
}

// ============================================================================
extern "C" void kernel_launch(void* const* d_in, const int* in_sizes, int n_in,
                              void* d_out, int out_size) {
    const float* x     = (const float*)d_in[0];
    const float* ln1_g = (const float*)d_in[3];
    const float* ln1_b = (const float*)d_in[4];
    const float* q_w   = (const float*)d_in[5];
    const float* q_b   = (const float*)d_in[6];
    const float* kv_w  = (const float*)d_in[7];
    const float* kv_b  = (const float*)d_in[8];
    const float* proj_w= (const float*)d_in[9];
    const float* proj_b= (const float*)d_in[10];
    const float* sr_w  = (const float*)d_in[11];
    const float* sr_b  = (const float*)d_in[12];
    const float* srn_g = (const float*)d_in[13];
    const float* srn_b = (const float*)d_in[14];
    const float* ln2_g = (const float*)d_in[15];
    const float* ln2_b = (const float*)d_in[16];
    const float* fc1_w = (const float*)d_in[17];
    const float* fc1_b = (const float*)d_in[18];
    const float* dw_w  = (const float*)d_in[19];
    const float* fc2_w = (const float*)d_in[20];
    const float* fc2_b = (const float*)d_in[21];
    float* outp = (float*)d_out;

    cudaFuncSetAttribute(k_srconv,  cudaFuncAttributeMaxDynamicSharedMemorySize, (16384+1024)*4);
    cudaFuncSetAttribute(k_attn,    cudaFuncAttributeMaxDynamicSharedMemorySize, ATTN_SMEM_BYTES);
    cudaFuncSetAttribute(k_ln2_fc1, cudaFuncAttributeMaxDynamicSharedMemorySize, FC1_SMEM_BYTES);
    cudaFuncSetAttribute(k_dw_fc2,  cudaFuncAttributeMaxDynamicSharedMemorySize, FC2_SMEM_BYTES);

    k_ln1_q  <<<BB*NN/64, 256>>>(x, ln1_g, ln1_b, q_w, q_b);
    k_srconv <<<BB*NRR/4, 256, (16384+1024)*4>>>(sr_w, sr_b);
    k_srn_kv <<<BB*NRR/8, 256>>>(srn_g, srn_b, kv_w, kv_b);
    k_attn   <<<dim3(NN/64, BB), 128, ATTN_SMEM_BYTES>>>(x, proj_w, proj_b);
    k_ln2_fc1<<<BB*NN/64, 256, FC1_SMEM_BYTES>>>(ln2_g, ln2_b, fc1_w, fc1_b);
    k_dw_fc2 <<<BB*NN/64, 256, FC2_SMEM_BYTES>>>(dw_w, fc2_w, fc2_b, outp);
}

// round 8
// speedup vs baseline: 4.9225x; 1.2190x over previous
#include <cuda_runtime.h>
#include <cuda_bf16.h>
#include <math.h>

#define BB   8
#define NN   16384
#define CC   64
#define HIDN 256
#define NRR  256

// ---------------- scratch (device globals; no allocs allowed) ----------------
__device__ float g_h [BB*NN*CC];                         // ln1 output (fp32, for srconv)
__device__ __align__(16) __nv_bfloat16 g_qb[BB*NN*CC];   // q bf16 (pre-scaled 0.125)
__device__ float g_sr[BB*NRR*CC];                        // sr conv output
__device__ __align__(16) __nv_bfloat16 g_kb[BB*NRR*CC];  // k bf16 [b][key][c]
__device__ __align__(16) __nv_bfloat16 g_vT[BB*CC*NRR];  // v bf16 transposed [b][c][key]
__device__ float g_x2[BB*NN*CC];                         // x + attn-proj residual (fp32)
__device__ __align__(16) __nv_bfloat16 g_fb[BB*NN*HIDN]; // fc1 output bf16
// prepped bf16 transposed weights
__device__ __align__(16) __nv_bfloat16 g_qwT[CC*CC];     // [cout][cin]
__device__ __align__(16) __nv_bfloat16 g_pwT[CC*CC];     // [cout][cin]
__device__ __align__(16) __nv_bfloat16 g_w1T[HIDN*CC];   // [cout][cin]
__device__ __align__(16) __nv_bfloat16 g_w2T[CC*HIDN];   // [cout][cin]

// ---------------- helpers ----------------
__device__ __forceinline__ void mma16816(float* c, const unsigned* a, unsigned b0, unsigned b1) {
    asm volatile("mma.sync.aligned.m16n8k16.row.col.f32.bf16.bf16.f32 "
        "{%0,%1,%2,%3}, {%4,%5,%6,%7}, {%8,%9}, {%0,%1,%2,%3};"
        : "+f"(c[0]), "+f"(c[1]), "+f"(c[2]), "+f"(c[3])
        : "r"(a[0]), "r"(a[1]), "r"(a[2]), "r"(a[3]), "r"(b0), "r"(b1));
}
__device__ __forceinline__ unsigned packbf(float lo, float hi) {
    unsigned r; asm("cvt.rn.bf16x2.f32 %0, %1, %2;" : "=r"(r) : "f"(hi), "f"(lo));
    return r;
}
__device__ __forceinline__ unsigned sptr(const void* p) {
    return (unsigned)__cvta_generic_to_shared(p);
}
__device__ __forceinline__ void ldsm4(unsigned* r, unsigned addr) {
    asm volatile("ldmatrix.sync.aligned.m8n8.x4.shared.b16 {%0,%1,%2,%3}, [%4];"
        : "=r"(r[0]), "=r"(r[1]), "=r"(r[2]), "=r"(r[3]) : "r"(addr));
}

// ============================================================================
// K0: weight prep -> bf16 transposed globals. 64 x 256 threads.
// ============================================================================
__global__ void k_prep(const float* __restrict__ qw, const float* __restrict__ pw,
                       const float* __restrict__ w1, const float* __restrict__ w2) {
    int i = blockIdx.x*256 + threadIdx.x;      // 0..16383
    if (i < 4096) {
        int ci = i >> 6, co = i & 63;
        g_qwT[co*64 + ci] = __float2bfloat16_rn(qw[i]);
        g_pwT[co*64 + ci] = __float2bfloat16_rn(pw[i]);
    }
    {   int ci = i >> 8, co = i & 255;          // fc1_w [cin][256]
        g_w1T[co*64 + ci] = __float2bfloat16_rn(w1[i]); }
    {   int ci = i >> 6, co = i & 63;           // fc2_w [cin][64]
        g_w2T[co*256 + ci] = __float2bfloat16_rn(w2[i]); }
}

// ============================================================================
// K1: LN1 (fp32) + q projection via bf16 mma. 128 threads, 64 rows/block.
// ============================================================================
__global__ void __launch_bounds__(128)
k_ln1_q(const float* __restrict__ x,
        const float* __restrict__ g1, const float* __restrict__ b1,
        const float* __restrict__ qb) {
    __shared__ __align__(16) __nv_bfloat16 hb[64*72];
    __shared__ __align__(16) __nv_bfloat16 wq[64*72];
    int t = threadIdx.x;
    for (int i = t; i < 512; i += 128) { int r = i>>3, j = (i&7)*8;
        *(uint4*)&wq[r*72+j] = *(const uint4*)&g_qwT[r*64+j]; }

    int row = t >> 1, half = t & 1;
    int grow = blockIdx.x*64 + row;
    const float4* xr4 = (const float4*)(x + (size_t)grow*64 + half*32);
    float xv[32]; float s = 0.f, ss = 0.f;
#pragma unroll
    for (int i4 = 0; i4 < 8; i4++) {
        float4 v = xr4[i4];
        xv[i4*4+0]=v.x; xv[i4*4+1]=v.y; xv[i4*4+2]=v.z; xv[i4*4+3]=v.w;
        s += v.x+v.y+v.z+v.w;
        ss += v.x*v.x+v.y*v.y+v.z*v.z+v.w*v.w;
    }
    s  += __shfl_xor_sync(0xffffffffu, s, 1);
    ss += __shfl_xor_sync(0xffffffffu, ss, 1);
    float mean = s * (1.0f/64.0f);
    float inv  = rsqrtf(ss * (1.0f/64.0f) - mean*mean + 1e-5f);
    float4* gh4 = (float4*)(g_h + (size_t)grow*64 + half*32);
    int c0 = half*32;
#pragma unroll
    for (int i4 = 0; i4 < 8; i4++) {
        float4 hv; float* hp = &hv.x;
#pragma unroll
        for (int i = 0; i < 4; i++) {
            int c = c0 + i4*4 + i;
            hp[i] = (xv[i4*4+i] - mean) * inv * g1[c] + b1[c];
        }
        gh4[i4] = hv;
        *(unsigned*)&hb[row*72 + c0 + i4*4]     = packbf(hv.x, hv.y);
        *(unsigned*)&hb[row*72 + c0 + i4*4 + 2] = packbf(hv.z, hv.w);
    }
    __syncthreads();

    int w = t >> 5, lane = t & 31;
    int g = lane >> 2, tt = lane & 3;
    int m0 = w * 16;
    int lane15 = lane & 15, hi8 = (lane & 16) ? 8 : 0;
    int l7 = lane & 7, lg8 = (lane >> 3) * 8;
    unsigned ah = sptr(hb), aw = sptr(wq);

    unsigned qa[4][4];
#pragma unroll
    for (int kc = 0; kc < 4; kc++)
        ldsm4(qa[kc], ah + ((m0+lane15)*72 + kc*16 + hi8)*2);

    float of[8][4] = {};
#pragma unroll
    for (int n = 0; n < 8; n++) {
        unsigned bb[8];
        ldsm4(bb,   aw + ((n*8+l7)*72 + lg8)*2);
        ldsm4(bb+4, aw + ((n*8+l7)*72 + 32 + lg8)*2);
        mma16816(of[n], qa[0], bb[0], bb[1]);
        mma16816(of[n], qa[1], bb[2], bb[3]);
        mma16816(of[n], qa[2], bb[4], bb[5]);
        mma16816(of[n], qa[3], bb[6], bb[7]);
    }
    int r0 = blockIdx.x*64 + m0 + g;
#pragma unroll
    for (int n = 0; n < 8; n++) {
        int col = n*8 + 2*tt;
        float2 qb2 = *(const float2*)(qb + col);
        *(unsigned*)&g_qb[(size_t)r0*64 + col] =
            packbf((of[n][0]+qb2.x)*0.125f, (of[n][1]+qb2.y)*0.125f);
        *(unsigned*)&g_qb[(size_t)(r0+8)*64 + col] =
            packbf((of[n][2]+qb2.x)*0.125f, (of[n][3]+qb2.y)*0.125f);
    }
}

// ============================================================================
// K2: spatial-reduction conv (8x8 s8). 4 output positions per block. (fp32)
// ============================================================================
__global__ void __launch_bounds__(256, 3)
k_srconv(const float* __restrict__ srw, const float* __restrict__ srb) {
    extern __shared__ float sm[];
    float* patch = sm;            // [4][4096]
    float* red   = sm + 16384;
    int grp = blockIdx.x;
    int b = grp >> 6; int p = grp & 63; int oy = p >> 2, ox0 = (p & 3)*4;
    int t = threadIdx.x;
    int c = t & 63, part = t >> 6;
    const float* hb = g_h + ((size_t)b * NN) * 64;
    for (int i = t; i < 4*4096; i += 256) {
        int pp = i >> 12, rem = i & 4095;
        int ij = rem >> 6, ci = rem & 63; int ii = ij >> 3, j = ij & 7;
        patch[i] = hb[((oy*8 + ii) * 128 + (ox0+pp)*8 + j) * 64 + ci];
    }
    __syncthreads();
    float a0=0.f, a1=0.f, a2=0.f, a3=0.f;
    int k0 = part * 1024;
#pragma unroll 8
    for (int k = k0; k < k0 + 1024; k++) {
        float w = srw[k*64 + c];
        a0 += patch[k]          * w;
        a1 += patch[4096 + k]   * w;
        a2 += patch[8192 + k]   * w;
        a3 += patch[12288 + k]  * w;
    }
    red[part*256 + 0*64 + c] = a0;
    red[part*256 + 1*64 + c] = a1;
    red[part*256 + 2*64 + c] = a2;
    red[part*256 + 3*64 + c] = a3;
    __syncthreads();
    {
        int pp = t >> 6, cc2 = t & 63;
        float r0 = red[0*256 + pp*64 + cc2] + red[1*256 + pp*64 + cc2]
                 + red[2*256 + pp*64 + cc2] + red[3*256 + pp*64 + cc2];
        int pos = b*256 + oy*16 + ox0 + pp;
        g_sr[pos*64 + cc2] = srb[cc2] + r0;
    }
}

// ============================================================================
// K3: LN over sr output + kv projection. Writes K bf16 + V bf16 transposed.
// ============================================================================
__global__ void k_srn_kv(const float* __restrict__ gs, const float* __restrict__ bs,
                         const float* __restrict__ kvw, const float* __restrict__ kvb) {
    __shared__ float ws[64*128];
    __shared__ float rowbuf[8][64];
    int t = threadIdx.x;
    for (int i = t; i < 8192; i += 256) ws[i] = kvw[i];
    __syncthreads();
    int warp = t >> 5, lane = t & 31;
    int r = blockIdx.x * 8 + warp;          // 0..2047
    const float* xr = g_sr + r * 64;
    float a0 = xr[lane], a1 = xr[lane + 32];
    float s = a0 + a1;
#pragma unroll
    for (int o = 16; o; o >>= 1) s += __shfl_xor_sync(0xffffffffu, s, o);
    float mean = s * (1.0f/64.0f);
    float d0 = a0 - mean, d1 = a1 - mean;
    float v = d0*d0 + d1*d1;
#pragma unroll
    for (int o = 16; o; o >>= 1) v += __shfl_xor_sync(0xffffffffu, v, o);
    float inv = rsqrtf(v * (1.0f/64.0f) + 1e-5f);
    float h0 = d0 * inv * gs[lane]      + bs[lane];
    float h1 = d1 * inv * gs[lane + 32] + bs[lane + 32];
    rowbuf[warp][lane]      = h0;
    rowbuf[warp][lane + 32] = h1;
    __syncwarp();
    float a  = kvb[lane], bq = kvb[lane+32], cv = kvb[lane+64], dv = kvb[lane+96];
#pragma unroll 8
    for (int ci = 0; ci < 64; ci++) {
        float hv = rowbuf[warp][ci];
        const float* w = ws + ci*128;
        a  += hv * w[lane];
        bq += hv * w[lane+32];
        cv += hv * w[lane+64];
        dv += hv * w[lane+96];
    }
    int b = r >> 8, key = r & 255;
    g_kb[r*64 + lane]      = __float2bfloat16_rn(a);
    g_kb[r*64 + lane + 32] = __float2bfloat16_rn(bq);
    g_vT[((size_t)b*64 + lane)*256 + key]      = __float2bfloat16_rn(cv);
    g_vT[((size_t)b*64 + lane + 32)*256 + key] = __float2bfloat16_rn(dv);
}

// ============================================================================
// K4: flash attention, 256 thr / 128 queries, resident bf16 K,V^T. ldmatrix.
// smem bf16: sq[128][72], sk[256][72], svT[64][264], swT[64][72] = 98304 B
// ============================================================================
#define ATTN_SMEM_BYTES ((128*72 + 256*72 + 64*264 + 64*72)*2)
__global__ void __launch_bounds__(256)
k_attn(const float* __restrict__ x, const float* __restrict__ pb) {
    extern __shared__ __align__(16) __nv_bfloat16 smA[];
    __nv_bfloat16* sq  = smA;                              // [128][72]
    __nv_bfloat16* sk  = smA + 128*72;                     // [256][72]
    __nv_bfloat16* svT = smA + 128*72 + 256*72;            // [64][264]
    __nv_bfloat16* swT = smA + 128*72 + 256*72 + 64*264;   // [64][72]

    int t = threadIdx.x;
    int b = blockIdx.y, qtile = blockIdx.x;
    int w = t >> 5, lane = t & 31;
    int g = lane >> 2, tt = lane & 3;
    int m0 = w * 16;
    int lane15 = lane & 15, hi8 = (lane & 16) ? 8 : 0;
    int l7 = lane & 7, lg8 = (lane >> 3) * 8;

    const __nv_bfloat16* qg = g_qb + ((size_t)b*NN + qtile*128)*64;
    const __nv_bfloat16* kg = g_kb + (size_t)b*256*64;
    const __nv_bfloat16* vg = g_vT + (size_t)b*64*256;
    for (int i = t; i < 1024; i += 256) { int r = i>>3, j = (i&7)*8;
        *(uint4*)&sq[r*72+j] = *(const uint4*)&qg[r*64+j]; }
    for (int i = t; i < 2048; i += 256) { int r = i>>3, j = (i&7)*8;
        *(uint4*)&sk[r*72+j] = *(const uint4*)&kg[r*64+j]; }
    for (int i = t; i < 2048; i += 256) { int r = i>>5, j = (i&31)*8;
        *(uint4*)&svT[r*264+j] = *(const uint4*)&vg[r*256+j]; }
    for (int i = t; i < 512; i += 256) { int r = i>>3, j = (i&7)*8;
        *(uint4*)&swT[r*72+j] = *(const uint4*)&g_pwT[r*64+j]; }
    __syncthreads();

    unsigned aq = sptr(sq), ak = sptr(sk), av = sptr(svT), aw = sptr(swT);
    unsigned qa[4][4];
#pragma unroll
    for (int kc = 0; kc < 4; kc++)
        ldsm4(qa[kc], aq + ((m0+lane15)*72 + kc*16 + hi8)*2);

    float mrow[2] = {-1e30f, -1e30f}, lrow[2] = {0.f, 0.f};
    float of[8][4] = {};

#pragma unroll 1
    for (int kt = 0; kt < 4; kt++) {
        int kk0 = kt*64;
        // S = Q K^T
        float sf[8][4] = {};
#pragma unroll
        for (int n = 0; n < 8; n++) {
            unsigned bb[8];
            ldsm4(bb,   ak + ((kk0+n*8+l7)*72 + lg8)*2);
            ldsm4(bb+4, ak + ((kk0+n*8+l7)*72 + 32 + lg8)*2);
            mma16816(sf[n], qa[0], bb[0], bb[1]);
            mma16816(sf[n], qa[1], bb[2], bb[3]);
            mma16816(sf[n], qa[2], bb[4], bb[5]);
            mma16816(sf[n], qa[3], bb[6], bb[7]);
        }
        // online softmax (rows g, g+8)
#pragma unroll
        for (int h = 0; h < 2; h++) {
            float tmax = -1e30f;
#pragma unroll
            for (int n = 0; n < 8; n++)
                tmax = fmaxf(tmax, fmaxf(sf[n][2*h], sf[n][2*h+1]));
            tmax = fmaxf(tmax, __shfl_xor_sync(0xffffffffu, tmax, 1));
            tmax = fmaxf(tmax, __shfl_xor_sync(0xffffffffu, tmax, 2));
            float newm = fmaxf(mrow[h], tmax);
            float scale = __expf(mrow[h] - newm);
            float sum = 0.f;
#pragma unroll
            for (int n = 0; n < 8; n++) {
                float e0 = __expf(sf[n][2*h]   - newm);
                float e1 = __expf(sf[n][2*h+1] - newm);
                sf[n][2*h] = e0; sf[n][2*h+1] = e1;
                sum += e0 + e1;
            }
            sum += __shfl_xor_sync(0xffffffffu, sum, 1);
            sum += __shfl_xor_sync(0xffffffffu, sum, 2);
            lrow[h] = lrow[h]*scale + sum;
            mrow[h] = newm;
#pragma unroll
            for (int n = 0; n < 8; n++) { of[n][2*h] *= scale; of[n][2*h+1] *= scale; }
        }
        // P C-frags -> A-frags in registers
        unsigned pa[4][4];
#pragma unroll
        for (int kc = 0; kc < 4; kc++) {
            pa[kc][0] = packbf(sf[2*kc][0],   sf[2*kc][1]);
            pa[kc][1] = packbf(sf[2*kc][2],   sf[2*kc][3]);
            pa[kc][2] = packbf(sf[2*kc+1][0], sf[2*kc+1][1]);
            pa[kc][3] = packbf(sf[2*kc+1][2], sf[2*kc+1][3]);
        }
        // O += P V
#pragma unroll
        for (int n = 0; n < 8; n++) {
            unsigned bb[8];
            ldsm4(bb,   av + ((n*8+l7)*264 + kk0 + lg8)*2);
            ldsm4(bb+4, av + ((n*8+l7)*264 + kk0 + 32 + lg8)*2);
            mma16816(of[n], pa[0], bb[0], bb[1]);
            mma16816(of[n], pa[1], bb[2], bb[3]);
            mma16816(of[n], pa[2], bb[4], bb[5]);
            mma16816(of[n], pa[3], bb[6], bb[7]);
        }
    }

    // normalize + out-projection + residual
    float rinv0 = 1.0f/lrow[0], rinv1 = 1.0f/lrow[1];
    unsigned oa[4][4];
#pragma unroll
    for (int kc = 0; kc < 4; kc++) {
        oa[kc][0] = packbf(of[2*kc][0]*rinv0,   of[2*kc][1]*rinv0);
        oa[kc][1] = packbf(of[2*kc][2]*rinv1,   of[2*kc][3]*rinv1);
        oa[kc][2] = packbf(of[2*kc+1][0]*rinv0, of[2*kc+1][1]*rinv0);
        oa[kc][3] = packbf(of[2*kc+1][2]*rinv1, of[2*kc+1][3]*rinv1);
    }
    float rf[8][4] = {};
#pragma unroll
    for (int n = 0; n < 8; n++) {
        unsigned bb[8];
        ldsm4(bb,   aw + ((n*8+l7)*72 + lg8)*2);
        ldsm4(bb+4, aw + ((n*8+l7)*72 + 32 + lg8)*2);
        mma16816(rf[n], oa[0], bb[0], bb[1]);
        mma16816(rf[n], oa[1], bb[2], bb[3]);
        mma16816(rf[n], oa[2], bb[4], bb[5]);
        mma16816(rf[n], oa[3], bb[6], bb[7]);
    }
    int row0 = qtile*128 + m0 + g;
#pragma unroll
    for (int n = 0; n < 8; n++) {
        int col = n*8 + 2*tt;
        float2 pbv = *(const float2*)(pb + col);
        size_t gi0 = ((size_t)b*NN + row0)*64 + col;
        float2 xv0 = *(const float2*)(x + gi0);
        float2 o0; o0.x = xv0.x + rf[n][0] + pbv.x; o0.y = xv0.y + rf[n][1] + pbv.y;
        *(float2*)(g_x2 + gi0) = o0;
        size_t gi1 = gi0 + 8*64;
        float2 xv1 = *(const float2*)(x + gi1);
        float2 o1; o1.x = xv1.x + rf[n][2] + pbv.x; o1.y = xv1.y + rf[n][3] + pbv.y;
        *(float2*)(g_x2 + gi1) = o1;
    }
}

// ============================================================================
// K5: LN2 (fp32) + fc1 via bf16 mma, prepped weights, ldmatrix. -> g_fb bf16
// smem: w1s[256][72] + h2[64][72] bf16 = 46080 B
// ============================================================================
#define FC1_SMEM_BYTES ((256*72 + 64*72)*2)
__global__ void __launch_bounds__(256)
k_ln2_fc1(const float* __restrict__ g2, const float* __restrict__ b2,
          const float* __restrict__ fc1b) {
    extern __shared__ __align__(16) __nv_bfloat16 smB[];
    __nv_bfloat16* w1s = smB;            // [cout 256][cin 72]
    __nv_bfloat16* h2  = smB + 256*72;   // [row 64][c 72]
    int t = threadIdx.x;
    for (int i = t; i < 2048; i += 256) { int r = i>>3, j = (i&7)*8;
        *(uint4*)&w1s[r*72+j] = *(const uint4*)&g_w1T[r*64+j]; }

    int row = t >> 2, q4 = t & 3;
    int grow = blockIdx.x*64 + row;
    float xv[16]; float s = 0.f, ss = 0.f;
    const float4* xr4 = (const float4*)(g_x2 + (size_t)grow*64 + q4*16);
#pragma unroll
    for (int i4 = 0; i4 < 4; i4++) {
        float4 v = xr4[i4];
        xv[i4*4+0]=v.x; xv[i4*4+1]=v.y; xv[i4*4+2]=v.z; xv[i4*4+3]=v.w;
        s += v.x+v.y+v.z+v.w;
        ss += v.x*v.x+v.y*v.y+v.z*v.z+v.w*v.w;
    }
    s  += __shfl_xor_sync(0xffffffffu, s, 1);  s  += __shfl_xor_sync(0xffffffffu, s, 2);
    ss += __shfl_xor_sync(0xffffffffu, ss, 1); ss += __shfl_xor_sync(0xffffffffu, ss, 2);
    float mean = s * (1.0f/64.0f);
    float inv  = rsqrtf(ss * (1.0f/64.0f) - mean*mean + 1e-5f);
    int c0 = q4*16;
#pragma unroll
    for (int i2 = 0; i2 < 8; i2++) {
        int c = c0 + 2*i2;
        float v0 = (xv[2*i2]   - mean) * inv * g2[c]   + b2[c];
        float v1 = (xv[2*i2+1] - mean) * inv * g2[c+1] + b2[c+1];
        *(unsigned*)&h2[row*72 + c] = packbf(v0, v1);
    }
    __syncthreads();

    int w = t >> 5, lane = t & 31;
    int g = lane >> 2, tt = lane & 3;
    int m0 = (w & 3) * 16, nbase = (w >> 2) * 128;
    int lane15 = lane & 15, hi8 = (lane & 16) ? 8 : 0;
    int l7 = lane & 7, lg8 = (lane >> 3) * 8;
    unsigned ah = sptr(h2), aw = sptr(w1s);

    unsigned qa[4][4];
#pragma unroll
    for (int kc = 0; kc < 4; kc++)
        ldsm4(qa[kc], ah + ((m0+lane15)*72 + kc*16 + hi8)*2);

    float of[16][4] = {};
#pragma unroll
    for (int n = 0; n < 16; n++) {
        int ncol = nbase + n*8;
        unsigned bb[8];
        ldsm4(bb,   aw + ((ncol+l7)*72 + lg8)*2);
        ldsm4(bb+4, aw + ((ncol+l7)*72 + 32 + lg8)*2);
        mma16816(of[n], qa[0], bb[0], bb[1]);
        mma16816(of[n], qa[1], bb[2], bb[3]);
        mma16816(of[n], qa[2], bb[4], bb[5]);
        mma16816(of[n], qa[3], bb[6], bb[7]);
    }
    int grow0 = blockIdx.x*64 + m0 + g;
#pragma unroll
    for (int n = 0; n < 16; n++) {
        int col = nbase + n*8 + 2*tt;
        float2 bv = *(const float2*)(fc1b + col);
        *(unsigned*)&g_fb[(size_t)grow0*256 + col] =
            packbf(of[n][0]+bv.x, of[n][1]+bv.y);
        *(unsigned*)&g_fb[(size_t)(grow0+8)*256 + col] =
            packbf(of[n][2]+bv.x, of[n][3]+bv.y);
    }
}

// ============================================================================
// K6: depthwise 3x3 SAME (fp32 rolling, bf16 in) + GELU -> bf16, fc2 via mma,
// + residual. smem: dws f32 9216 + w2s[64][264] + gg[64][264] bf16 = 76800 B
// ============================================================================
#define FC2_SMEM_BYTES (9216 + (64*264)*2*2)
__global__ void __launch_bounds__(256)
k_dw_fc2(const float* __restrict__ dww, const float* __restrict__ fc2b,
         float* __restrict__ outp) {
    extern __shared__ __align__(16) char smC[];
    float* dws = (float*)smC;                                    // [9][256]
    __nv_bfloat16* w2s = (__nv_bfloat16*)(smC + 9216);           // [cout 64][ci 264]
    __nv_bfloat16* gg  = (__nv_bfloat16*)(smC + 9216 + 64*264*2);// [tok 64][ci 264]
    int t = threadIdx.x;
    for (int i = t; i < 2304; i += 256) dws[i] = dww[i];
    for (int i = t; i < 2048; i += 256) { int r = i>>5, j = (i&31)*8;
        *(uint4*)&w2s[r*264+j] = *(const uint4*)&g_w2T[r*256+j]; }
    __syncthreads();

    int tok0 = blockIdx.x * 64;
    int b = tok0 >> 14; int rem = tok0 & 16383; int y = rem >> 7; int x0 = rem & 127;
    const __nv_bfloat16* fb = g_fb + (size_t)b * NN * HIDN;

    // ---- depthwise conv (rolling column dots) + GELU, t = channel ----
    {
        int ci = t;
        float w00 = dws[0*256+ci], w01 = dws[1*256+ci], w02 = dws[2*256+ci];
        float w10 = dws[3*256+ci], w11 = dws[4*256+ci], w12 = dws[5*256+ci];
        float w20 = dws[6*256+ci], w21 = dws[7*256+ci], w22 = dws[8*256+ci];
        bool y0ok = (y > 0), y2ok = (y < 127);
        float A = 0.f, Bc = 0.f, Cn = 0.f;
        const __nv_bfloat16* fr0 = fb + ((size_t)(y-1)*128)*256 + ci;
        const __nv_bfloat16* fr1 = fb + ((size_t) y   *128)*256 + ci;
        const __nv_bfloat16* fr2 = fb + ((size_t)(y+1)*128)*256 + ci;
#pragma unroll 4
        for (int c = x0-1; c <= x0+64; c++) {
            float a0 = 0.f, a1 = 0.f, a2 = 0.f;
            if ((unsigned)c < 128u) {
                float f0 = y0ok ? __bfloat162float(fr0[(size_t)c*256]) : 0.f;
                float f1 = __bfloat162float(fr1[(size_t)c*256]);
                float f2 = y2ok ? __bfloat162float(fr2[(size_t)c*256]) : 0.f;
                a0 = f0*w00 + f1*w10 + f2*w20;
                a1 = f0*w01 + f1*w11 + f2*w21;
                a2 = f0*w02 + f1*w12 + f2*w22;
            }
            A += a2; Bc += a1; Cn += a0;
            int xo = c - 1;
            if (xo >= x0 && xo < x0 + 64) {
                float v = A;
                float ge = 0.5f * v * (1.0f + erff(v * 0.70710678118654752f));
                gg[(xo - x0)*264 + ci] = __float2bfloat16_rn(ge);
            }
            A = Bc; Bc = Cn; Cn = 0.f;
        }
    }
    __syncthreads();

    // ---- fc2 GEMM via mma + ldmatrix ----
    int w = t >> 5, lane = t & 31;
    int g = lane >> 2, tt = lane & 3;
    int m0 = (w & 3) * 16, nbase = (w >> 2) * 32;
    int lane15 = lane & 15, hi8 = (lane & 16) ? 8 : 0;
    int l7 = lane & 7, lg8 = (lane >> 3) * 8;
    unsigned ag = sptr(gg), aw2 = sptr(w2s);

    float of[4][4] = {};
#pragma unroll
    for (int kc2 = 0; kc2 < 8; kc2++) {
        unsigned A0[4], A1[4];
        ldsm4(A0, ag + ((m0+lane15)*264 + (2*kc2)*16 + hi8)*2);
        ldsm4(A1, ag + ((m0+lane15)*264 + (2*kc2+1)*16 + hi8)*2);
#pragma unroll
        for (int n = 0; n < 4; n++) {
            unsigned bb[4];
            ldsm4(bb, aw2 + ((nbase + n*8 + l7)*264 + (2*kc2)*16 + lg8)*2);
            mma16816(of[n], A0, bb[0], bb[1]);
            mma16816(of[n], A1, bb[2], bb[3]);
        }
    }
    int tok = tok0 + m0 + g;
#pragma unroll
    for (int n = 0; n < 4; n++) {
        int col = nbase + n*8 + 2*tt;
        float2 bv = *(const float2*)(fc2b + col);
        size_t gi0 = (size_t)tok*64 + col;
        float2 xv0 = *(const float2*)(g_x2 + gi0);
        float2 o0; o0.x = xv0.x + of[n][0] + bv.x; o0.y = xv0.y + of[n][1] + bv.y;
        *(float2*)(outp + gi0) = o0;
        size_t gi1 = gi0 + 8*64;
        float2 xv1 = *(const float2*)(g_x2 + gi1);
        float2 o1; o1.x = xv1.x + of[n][2] + bv.x; o1.y = xv1.y + of[n][3] + bv.y;
        *(float2*)(outp + gi1) = o1;
    }
}

// ============================================================================
extern "C" void kernel_launch(void* const* d_in, const int* in_sizes, int n_in,
                              void* d_out, int out_size) {
    const float* x     = (const float*)d_in[0];
    const float* ln1_g = (const float*)d_in[3];
    const float* ln1_b = (const float*)d_in[4];
    const float* q_w   = (const float*)d_in[5];
    const float* q_b   = (const float*)d_in[6];
    const float* kv_w  = (const float*)d_in[7];
    const float* kv_b  = (const float*)d_in[8];
    const float* proj_w= (const float*)d_in[9];
    const float* proj_b= (const float*)d_in[10];
    const float* sr_w  = (const float*)d_in[11];
    const float* sr_b  = (const float*)d_in[12];
    const float* srn_g = (const float*)d_in[13];
    const float* srn_b = (const float*)d_in[14];
    const float* ln2_g = (const float*)d_in[15];
    const float* ln2_b = (const float*)d_in[16];
    const float* fc1_w = (const float*)d_in[17];
    const float* fc1_b = (const float*)d_in[18];
    const float* dw_w  = (const float*)d_in[19];
    const float* fc2_w = (const float*)d_in[20];
    const float* fc2_b = (const float*)d_in[21];
    float* outp = (float*)d_out;

    cudaFuncSetAttribute(k_srconv,  cudaFuncAttributeMaxDynamicSharedMemorySize, (16384+1024)*4);
    cudaFuncSetAttribute(k_attn,    cudaFuncAttributeMaxDynamicSharedMemorySize, ATTN_SMEM_BYTES);
    cudaFuncSetAttribute(k_ln2_fc1, cudaFuncAttributeMaxDynamicSharedMemorySize, FC1_SMEM_BYTES);
    cudaFuncSetAttribute(k_dw_fc2,  cudaFuncAttributeMaxDynamicSharedMemorySize, FC2_SMEM_BYTES);

    k_prep   <<<64, 256>>>(q_w, proj_w, fc1_w, fc2_w);
    k_ln1_q  <<<BB*NN/64, 128>>>(x, ln1_g, ln1_b, q_b);
    k_srconv <<<BB*NRR/4, 256, (16384+1024)*4>>>(sr_w, sr_b);
    k_srn_kv <<<BB*NRR/8, 256>>>(srn_g, srn_b, kv_w, kv_b);
    k_attn   <<<dim3(NN/128, BB), 256, ATTN_SMEM_BYTES>>>(x, proj_b);
    k_ln2_fc1<<<BB*NN/64, 256, FC1_SMEM_BYTES>>>(ln2_g, ln2_b, fc1_b);
    k_dw_fc2 <<<BB*NN/64, 256, FC2_SMEM_BYTES>>>(dw_w, fc2_b, outp);
}

// round 11
// speedup vs baseline: 6.0136x; 1.2216x over previous
#include <cuda_runtime.h>
#include <cuda_bf16.h>
#include <math.h>

#define BB   8
#define NN   16384
#define CC   64
#define HIDN 256
#define NRR  256

// ---------------- scratch (device globals; no allocs allowed) ----------------
__device__ __align__(16) __nv_bfloat16 g_hb[BB*NN*CC];   // ln1 output bf16 (srconv input)
__device__ __align__(16) __nv_bfloat16 g_qb[BB*NN*CC];   // q bf16 (pre-scaled 0.125)
__device__ float g_sr[BB*NRR*CC];                        // sr conv output
__device__ __align__(16) __nv_bfloat16 g_kb[BB*NRR*CC];  // k bf16 [b][key][c]
__device__ __align__(16) __nv_bfloat16 g_vT[BB*CC*NRR];  // v bf16 transposed [b][c][key]
__device__ float g_x2[BB*NN*CC];                         // x + attn-proj residual (fp32)
__device__ __align__(16) __nv_bfloat16 g_fb[BB*NN*HIDN]; // fc1 output bf16
// prepped bf16 transposed weights
__device__ __align__(16) __nv_bfloat16 g_qwT[CC*CC];       // [cout][cin]
__device__ __align__(16) __nv_bfloat16 g_pwT[CC*CC];       // [cout][cin]
__device__ __align__(16) __nv_bfloat16 g_w1T[HIDN*CC];     // [cout][cin]
__device__ __align__(16) __nv_bfloat16 g_w2T[CC*HIDN];     // [cout][cin]
__device__ __align__(16) __nv_bfloat16 g_srwT[CC*4096];    // sr_w transposed [cout][k=4096]

// ---------------- helpers ----------------
__device__ __forceinline__ void mma16816(float* c, const unsigned* a, unsigned b0, unsigned b1) {
    asm volatile("mma.sync.aligned.m16n8k16.row.col.f32.bf16.bf16.f32 "
        "{%0,%1,%2,%3}, {%4,%5,%6,%7}, {%8,%9}, {%0,%1,%2,%3};"
        : "+f"(c[0]), "+f"(c[1]), "+f"(c[2]), "+f"(c[3])
        : "r"(a[0]), "r"(a[1]), "r"(a[2]), "r"(a[3]), "r"(b0), "r"(b1));
}
__device__ __forceinline__ unsigned packbf(float lo, float hi) {
    unsigned r; asm("cvt.rn.bf16x2.f32 %0, %1, %2;" : "=r"(r) : "f"(hi), "f"(lo));
    return r;
}
__device__ __forceinline__ unsigned sptr(const void* p) {
    return (unsigned)__cvta_generic_to_shared(p);
}
__device__ __forceinline__ void ldsm4(unsigned* r, unsigned addr) {
    asm volatile("ldmatrix.sync.aligned.m8n8.x4.shared.b16 {%0,%1,%2,%3}, [%4];"
        : "=r"(r[0]), "=r"(r[1]), "=r"(r[2]), "=r"(r[3]) : "r"(addr));
}

// ============================================================================
// K0: weight prep -> bf16 transposed globals. 1024 x 256 threads.
// ============================================================================
__global__ void k_prep(const float* __restrict__ qw, const float* __restrict__ pw,
                       const float* __restrict__ w1, const float* __restrict__ w2,
                       const float* __restrict__ srw) {
    int i = blockIdx.x*256 + threadIdx.x;      // 0..262143
    if (i < 4096) {
        int ci = i >> 6, co = i & 63;
        g_qwT[co*64 + ci] = __float2bfloat16_rn(qw[i]);
        g_pwT[co*64 + ci] = __float2bfloat16_rn(pw[i]);
    }
    if (i < 16384) {
        { int ci = i >> 8, co = i & 255;        // fc1_w [cin][256]
          g_w1T[co*64 + ci] = __float2bfloat16_rn(w1[i]); }
        { int ci = i >> 6, co = i & 63;         // fc2_w [cin][64]
          g_w2T[co*256 + ci] = __float2bfloat16_rn(w2[i]); }
    }
    {   // sr_w [k=4096][co=64] -> g_srwT [co][k]
        int k = i >> 6, co = i & 63;
        g_srwT[co*4096 + k] = __float2bfloat16_rn(srw[i]);
    }
}

// ============================================================================
// K1: LN1 (fp32) + q projection via bf16 mma. 128 threads, 64 rows/block.
// Writes h as bf16 (g_hb) and q as bf16 (g_qb).
// ============================================================================
__global__ void __launch_bounds__(128)
k_ln1_q(const float* __restrict__ x,
        const float* __restrict__ g1, const float* __restrict__ b1,
        const float* __restrict__ qb) {
    __shared__ __align__(16) __nv_bfloat16 hb[64*72];
    __shared__ __align__(16) __nv_bfloat16 wq[64*72];
    int t = threadIdx.x;
    for (int i = t; i < 512; i += 128) { int r = i>>3, j = (i&7)*8;
        *(uint4*)&wq[r*72+j] = *(const uint4*)&g_qwT[r*64+j]; }

    int row = t >> 1, half = t & 1;
    int grow = blockIdx.x*64 + row;
    const float4* xr4 = (const float4*)(x + (size_t)grow*64 + half*32);
    float xv[32]; float s = 0.f, ss = 0.f;
#pragma unroll
    for (int i4 = 0; i4 < 8; i4++) {
        float4 v = xr4[i4];
        xv[i4*4+0]=v.x; xv[i4*4+1]=v.y; xv[i4*4+2]=v.z; xv[i4*4+3]=v.w;
        s += v.x+v.y+v.z+v.w;
        ss += v.x*v.x+v.y*v.y+v.z*v.z+v.w*v.w;
    }
    s  += __shfl_xor_sync(0xffffffffu, s, 1);
    ss += __shfl_xor_sync(0xffffffffu, ss, 1);
    float mean = s * (1.0f/64.0f);
    float inv  = rsqrtf(ss * (1.0f/64.0f) - mean*mean + 1e-5f);
    int c0 = half*32;
#pragma unroll
    for (int i4 = 0; i4 < 8; i4++) {
        float h0 = (xv[i4*4+0] - mean) * inv * g1[c0+i4*4+0] + b1[c0+i4*4+0];
        float h1 = (xv[i4*4+1] - mean) * inv * g1[c0+i4*4+1] + b1[c0+i4*4+1];
        float h2 = (xv[i4*4+2] - mean) * inv * g1[c0+i4*4+2] + b1[c0+i4*4+2];
        float h3 = (xv[i4*4+3] - mean) * inv * g1[c0+i4*4+3] + b1[c0+i4*4+3];
        unsigned p0 = packbf(h0, h1), p1 = packbf(h2, h3);
        *(unsigned*)&hb[row*72 + c0 + i4*4]     = p0;
        *(unsigned*)&hb[row*72 + c0 + i4*4 + 2] = p1;
        *(unsigned*)&g_hb[(size_t)grow*64 + c0 + i4*4]     = p0;
        *(unsigned*)&g_hb[(size_t)grow*64 + c0 + i4*4 + 2] = p1;
    }
    __syncthreads();

    int w = t >> 5, lane = t & 31;
    int g = lane >> 2, tt = lane & 3;
    int m0 = w * 16;
    int lane15 = lane & 15, hi8 = (lane & 16) ? 8 : 0;
    int l7 = lane & 7, lg8 = (lane >> 3) * 8;
    unsigned ah = sptr(hb), aw = sptr(wq);

    unsigned qa[4][4];
#pragma unroll
    for (int kc = 0; kc < 4; kc++)
        ldsm4(qa[kc], ah + ((m0+lane15)*72 + kc*16 + hi8)*2);

    float of[8][4] = {};
#pragma unroll
    for (int n = 0; n < 8; n++) {
        unsigned bb[8];
        ldsm4(bb,   aw + ((n*8+l7)*72 + lg8)*2);
        ldsm4(bb+4, aw + ((n*8+l7)*72 + 32 + lg8)*2);
        mma16816(of[n], qa[0], bb[0], bb[1]);
        mma16816(of[n], qa[1], bb[2], bb[3]);
        mma16816(of[n], qa[2], bb[4], bb[5]);
        mma16816(of[n], qa[3], bb[6], bb[7]);
    }
    int r0 = blockIdx.x*64 + m0 + g;
#pragma unroll
    for (int n = 0; n < 8; n++) {
        int col = n*8 + 2*tt;
        float2 qb2 = *(const float2*)(qb + col);
        *(unsigned*)&g_qb[(size_t)r0*64 + col] =
            packbf((of[n][0]+qb2.x)*0.125f, (of[n][1]+qb2.y)*0.125f);
        *(unsigned*)&g_qb[(size_t)(r0+8)*64 + col] =
            packbf((of[n][2]+qb2.x)*0.125f, (of[n][3]+qb2.y)*0.125f);
    }
}

// ============================================================================
// K2: spatial-reduction conv as bf16 mma GEMM: [2048 pos] x [64 cout] x K=4096.
// 64 blocks x 32 positions; K streamed in 16 chunks of 256.
// smem: sA [32][264] + sW [64][264] bf16 = 50688 B
// ============================================================================
#define SRC_SMEM_BYTES ((32*264 + 64*264)*2)
__global__ void __launch_bounds__(256)
k_srconv(const float* __restrict__ srb) {
    extern __shared__ __align__(16) __nv_bfloat16 smS[];
    __nv_bfloat16* sA = smS;            // [pos 32][k 264]
    __nv_bfloat16* sW = smS + 32*264;   // [cout 64][k 264]
    int t = threadIdx.x;
    int b = blockIdx.x >> 3;            // batch
    int p0 = (blockIdx.x & 7) * 32;     // first position within batch (2 oy rows)
    const __nv_bfloat16* hbase = g_hb + ((size_t)b * NN) * 64;

    int w = t >> 5, lane = t & 31;
    int g = lane >> 2, tt = lane & 3;
    int m0 = (w & 1) * 16, ncol0 = (w >> 1) * 16;
    int lane15 = lane & 15, hi8 = (lane & 16) ? 8 : 0;
    int l7 = lane & 7, lg8 = (lane >> 3) * 8;
    unsigned aA = sptr(sA), aW = sptr(sW);

    float of[2][4] = {};

#pragma unroll 1
    for (int kc = 0; kc < 16; kc++) {
        // fill A chunk: 32 pos x 256 k (k = ij*64+ci; 4 ij per chunk)
#pragma unroll
        for (int u0 = 0; u0 < 4; u0++) {
            int u = u0*256 + t;                 // 0..1023 uint4
            int row = u >> 5, seg = (u >> 3) & 3, e = u & 7;
            int p = p0 + row, oy = p >> 4, ox = p & 15;
            int ij = kc*4 + seg, ii = ij >> 3, jj = ij & 7;
            *(uint4*)&sA[row*264 + seg*64 + e*8] =
                *(const uint4*)&hbase[((size_t)(oy*8+ii)*128 + ox*8+jj)*64 + e*8];
        }
        // fill W chunk: 64 cout x 256 k
#pragma unroll
        for (int u0 = 0; u0 < 8; u0++) {
            int u = u0*256 + t;                 // 0..2047 uint4
            int co = u >> 5, e = u & 31;
            *(uint4*)&sW[co*264 + e*8] =
                *(const uint4*)&g_srwT[(size_t)co*4096 + kc*256 + e*8];
        }
        __syncthreads();
#pragma unroll
        for (int ks = 0; ks < 8; ks++) {        // 8 x 32k
            unsigned A0[4], A1[4];
            ldsm4(A0, aA + ((m0+lane15)*264 + (2*ks)*16 + hi8)*2);
            ldsm4(A1, aA + ((m0+lane15)*264 + (2*ks+1)*16 + hi8)*2);
#pragma unroll
            for (int n = 0; n < 2; n++) {
                unsigned bb[4];
                ldsm4(bb, aW + ((ncol0+n*8+l7)*264 + (2*ks)*16 + lg8)*2);
                mma16816(of[n], A0, bb[0], bb[1]);
                mma16816(of[n], A1, bb[2], bb[3]);
            }
        }
        __syncthreads();
    }

    int prow = p0 + m0 + g;                     // position within batch
#pragma unroll
    for (int n = 0; n < 2; n++) {
        int col = ncol0 + n*8 + 2*tt;
        float2 bv = *(const float2*)(srb + col);
        size_t gi0 = ((size_t)b*256 + prow)*64 + col;
        float2 o0; o0.x = of[n][0] + bv.x; o0.y = of[n][1] + bv.y;
        *(float2*)(g_sr + gi0) = o0;
        size_t gi1 = gi0 + 8*64;
        float2 o1; o1.x = of[n][2] + bv.x; o1.y = of[n][3] + bv.y;
        *(float2*)(g_sr + gi1) = o1;
    }
}

// ============================================================================
// K3: LN over sr output + kv projection. Writes K bf16 + V bf16 transposed.
// ============================================================================
__global__ void k_srn_kv(const float* __restrict__ gs, const float* __restrict__ bs,
                         const float* __restrict__ kvw, const float* __restrict__ kvb) {
    __shared__ float ws[64*128];
    __shared__ float rowbuf[8][64];
    int t = threadIdx.x;
    for (int i = t; i < 8192; i += 256) ws[i] = kvw[i];
    __syncthreads();
    int warp = t >> 5, lane = t & 31;
    int r = blockIdx.x * 8 + warp;          // 0..2047
    const float* xr = g_sr + r * 64;
    float a0 = xr[lane], a1 = xr[lane + 32];
    float s = a0 + a1;
#pragma unroll
    for (int o = 16; o; o >>= 1) s += __shfl_xor_sync(0xffffffffu, s, o);
    float mean = s * (1.0f/64.0f);
    float d0 = a0 - mean, d1 = a1 - mean;
    float v = d0*d0 + d1*d1;
#pragma unroll
    for (int o = 16; o; o >>= 1) v += __shfl_xor_sync(0xffffffffu, v, o);
    float inv = rsqrtf(v * (1.0f/64.0f) + 1e-5f);
    float h0 = d0 * inv * gs[lane]      + bs[lane];
    float h1 = d1 * inv * gs[lane + 32] + bs[lane + 32];
    rowbuf[warp][lane]      = h0;
    rowbuf[warp][lane + 32] = h1;
    __syncwarp();
    float a  = kvb[lane], bq = kvb[lane+32], cv = kvb[lane+64], dv = kvb[lane+96];
#pragma unroll 8
    for (int ci = 0; ci < 64; ci++) {
        float hv = rowbuf[warp][ci];
        const float* w = ws + ci*128;
        a  += hv * w[lane];
        bq += hv * w[lane+32];
        cv += hv * w[lane+64];
        dv += hv * w[lane+96];
    }
    int b = r >> 8, key = r & 255;
    g_kb[r*64 + lane]      = __float2bfloat16_rn(a);
    g_kb[r*64 + lane + 32] = __float2bfloat16_rn(bq);
    g_vT[((size_t)b*64 + lane)*256 + key]      = __float2bfloat16_rn(cv);
    g_vT[((size_t)b*64 + lane + 32)*256 + key] = __float2bfloat16_rn(dv);
}

// ============================================================================
// K4: flash attention, 256 thr / 128 queries, resident bf16 K,V^T. ldmatrix.
// smem bf16: sq[128][72], sk[256][72], svT[64][264], swT[64][72] = 98304 B
// ============================================================================
#define ATTN_SMEM_BYTES ((128*72 + 256*72 + 64*264 + 64*72)*2)
__global__ void __launch_bounds__(256)
k_attn(const float* __restrict__ x, const float* __restrict__ pb) {
    extern __shared__ __align__(16) __nv_bfloat16 smA[];
    __nv_bfloat16* sq  = smA;                              // [128][72]
    __nv_bfloat16* sk  = smA + 128*72;                     // [256][72]
    __nv_bfloat16* svT = smA + 128*72 + 256*72;            // [64][264]
    __nv_bfloat16* swT = smA + 128*72 + 256*72 + 64*264;   // [64][72]

    int t = threadIdx.x;
    int b = blockIdx.y, qtile = blockIdx.x;
    int w = t >> 5, lane = t & 31;
    int g = lane >> 2, tt = lane & 3;
    int m0 = w * 16;
    int lane15 = lane & 15, hi8 = (lane & 16) ? 8 : 0;
    int l7 = lane & 7, lg8 = (lane >> 3) * 8;

    const __nv_bfloat16* qg = g_qb + ((size_t)b*NN + qtile*128)*64;
    const __nv_bfloat16* kg = g_kb + (size_t)b*256*64;
    const __nv_bfloat16* vg = g_vT + (size_t)b*64*256;
    for (int i = t; i < 1024; i += 256) { int r = i>>3, j = (i&7)*8;
        *(uint4*)&sq[r*72+j] = *(const uint4*)&qg[r*64+j]; }
    for (int i = t; i < 2048; i += 256) { int r = i>>3, j = (i&7)*8;
        *(uint4*)&sk[r*72+j] = *(const uint4*)&kg[r*64+j]; }
    for (int i = t; i < 2048; i += 256) { int r = i>>5, j = (i&31)*8;
        *(uint4*)&svT[r*264+j] = *(const uint4*)&vg[r*256+j]; }
    for (int i = t; i < 512; i += 256) { int r = i>>3, j = (i&7)*8;
        *(uint4*)&swT[r*72+j] = *(const uint4*)&g_pwT[r*64+j]; }
    __syncthreads();

    unsigned aq = sptr(sq), ak = sptr(sk), av = sptr(svT), aw = sptr(swT);
    unsigned qa[4][4];
#pragma unroll
    for (int kc = 0; kc < 4; kc++)
        ldsm4(qa[kc], aq + ((m0+lane15)*72 + kc*16 + hi8)*2);

    float mrow[2] = {-1e30f, -1e30f}, lrow[2] = {0.f, 0.f};
    float of[8][4] = {};

#pragma unroll 1
    for (int kt = 0; kt < 4; kt++) {
        int kk0 = kt*64;
        // S = Q K^T
        float sf[8][4] = {};
#pragma unroll
        for (int n = 0; n < 8; n++) {
            unsigned bb[8];
            ldsm4(bb,   ak + ((kk0+n*8+l7)*72 + lg8)*2);
            ldsm4(bb+4, ak + ((kk0+n*8+l7)*72 + 32 + lg8)*2);
            mma16816(sf[n], qa[0], bb[0], bb[1]);
            mma16816(sf[n], qa[1], bb[2], bb[3]);
            mma16816(sf[n], qa[2], bb[4], bb[5]);
            mma16816(sf[n], qa[3], bb[6], bb[7]);
        }
        // online softmax (rows g, g+8)
#pragma unroll
        for (int h = 0; h < 2; h++) {
            float tmax = -1e30f;
#pragma unroll
            for (int n = 0; n < 8; n++)
                tmax = fmaxf(tmax, fmaxf(sf[n][2*h], sf[n][2*h+1]));
            tmax = fmaxf(tmax, __shfl_xor_sync(0xffffffffu, tmax, 1));
            tmax = fmaxf(tmax, __shfl_xor_sync(0xffffffffu, tmax, 2));
            float newm = fmaxf(mrow[h], tmax);
            float scale = __expf(mrow[h] - newm);
            float sum = 0.f;
#pragma unroll
            for (int n = 0; n < 8; n++) {
                float e0 = __expf(sf[n][2*h]   - newm);
                float e1 = __expf(sf[n][2*h+1] - newm);
                sf[n][2*h] = e0; sf[n][2*h+1] = e1;
                sum += e0 + e1;
            }
            sum += __shfl_xor_sync(0xffffffffu, sum, 1);
            sum += __shfl_xor_sync(0xffffffffu, sum, 2);
            lrow[h] = lrow[h]*scale + sum;
            mrow[h] = newm;
#pragma unroll
            for (int n = 0; n < 8; n++) { of[n][2*h] *= scale; of[n][2*h+1] *= scale; }
        }
        // P C-frags -> A-frags in registers
        unsigned pa[4][4];
#pragma unroll
        for (int kc = 0; kc < 4; kc++) {
            pa[kc][0] = packbf(sf[2*kc][0],   sf[2*kc][1]);
            pa[kc][1] = packbf(sf[2*kc][2],   sf[2*kc][3]);
            pa[kc][2] = packbf(sf[2*kc+1][0], sf[2*kc+1][1]);
            pa[kc][3] = packbf(sf[2*kc+1][2], sf[2*kc+1][3]);
        }
        // O += P V
#pragma unroll
        for (int n = 0; n < 8; n++) {
            unsigned bb[8];
            ldsm4(bb,   av + ((n*8+l7)*264 + kk0 + lg8)*2);
            ldsm4(bb+4, av + ((n*8+l7)*264 + kk0 + 32 + lg8)*2);
            mma16816(of[n], pa[0], bb[0], bb[1]);
            mma16816(of[n], pa[1], bb[2], bb[3]);
            mma16816(of[n], pa[2], bb[4], bb[5]);
            mma16816(of[n], pa[3], bb[6], bb[7]);
        }
    }

    // normalize + out-projection + residual
    float rinv0 = 1.0f/lrow[0], rinv1 = 1.0f/lrow[1];
    unsigned oa[4][4];
#pragma unroll
    for (int kc = 0; kc < 4; kc++) {
        oa[kc][0] = packbf(of[2*kc][0]*rinv0,   of[2*kc][1]*rinv0);
        oa[kc][1] = packbf(of[2*kc][2]*rinv1,   of[2*kc][3]*rinv1);
        oa[kc][2] = packbf(of[2*kc+1][0]*rinv0, of[2*kc+1][1]*rinv0);
        oa[kc][3] = packbf(of[2*kc+1][2]*rinv1, of[2*kc+1][3]*rinv1);
    }
    float rf[8][4] = {};
#pragma unroll
    for (int n = 0; n < 8; n++) {
        unsigned bb[8];
        ldsm4(bb,   aw + ((n*8+l7)*72 + lg8)*2);
        ldsm4(bb+4, aw + ((n*8+l7)*72 + 32 + lg8)*2);
        mma16816(rf[n], oa[0], bb[0], bb[1]);
        mma16816(rf[n], oa[1], bb[2], bb[3]);
        mma16816(rf[n], oa[2], bb[4], bb[5]);
        mma16816(rf[n], oa[3], bb[6], bb[7]);
    }
    int row0 = qtile*128 + m0 + g;
#pragma unroll
    for (int n = 0; n < 8; n++) {
        int col = n*8 + 2*tt;
        float2 pbv = *(const float2*)(pb + col);
        size_t gi0 = ((size_t)b*NN + row0)*64 + col;
        float2 xv0 = *(const float2*)(x + gi0);
        float2 o0; o0.x = xv0.x + rf[n][0] + pbv.x; o0.y = xv0.y + rf[n][1] + pbv.y;
        *(float2*)(g_x2 + gi0) = o0;
        size_t gi1 = gi0 + 8*64;
        float2 xv1 = *(const float2*)(x + gi1);
        float2 o1; o1.x = xv1.x + rf[n][2] + pbv.x; o1.y = xv1.y + rf[n][3] + pbv.y;
        *(float2*)(g_x2 + gi1) = o1;
    }
}

// ============================================================================
// K5: LN2 (fp32) + fc1 via bf16 mma, prepped weights, ldmatrix. -> g_fb bf16
// smem: w1s[256][72] + h2[64][72] bf16 = 46080 B
// ============================================================================
#define FC1_SMEM_BYTES ((256*72 + 64*72)*2)
__global__ void __launch_bounds__(256)
k_ln2_fc1(const float* __restrict__ g2, const float* __restrict__ b2,
          const float* __restrict__ fc1b) {
    extern __shared__ __align__(16) __nv_bfloat16 smB[];
    __nv_bfloat16* w1s = smB;            // [cout 256][cin 72]
    __nv_bfloat16* h2  = smB + 256*72;   // [row 64][c 72]
    int t = threadIdx.x;
    for (int i = t; i < 2048; i += 256) { int r = i>>3, j = (i&7)*8;
        *(uint4*)&w1s[r*72+j] = *(const uint4*)&g_w1T[r*64+j]; }

    int row = t >> 2, q4 = t & 3;
    int grow = blockIdx.x*64 + row;
    float xv[16]; float s = 0.f, ss = 0.f;
    const float4* xr4 = (const float4*)(g_x2 + (size_t)grow*64 + q4*16);
#pragma unroll
    for (int i4 = 0; i4 < 4; i4++) {
        float4 v = xr4[i4];
        xv[i4*4+0]=v.x; xv[i4*4+1]=v.y; xv[i4*4+2]=v.z; xv[i4*4+3]=v.w;
        s += v.x+v.y+v.z+v.w;
        ss += v.x*v.x+v.y*v.y+v.z*v.z+v.w*v.w;
    }
    s  += __shfl_xor_sync(0xffffffffu, s, 1);  s  += __shfl_xor_sync(0xffffffffu, s, 2);
    ss += __shfl_xor_sync(0xffffffffu, ss, 1); ss += __shfl_xor_sync(0xffffffffu, ss, 2);
    float mean = s * (1.0f/64.0f);
    float inv  = rsqrtf(ss * (1.0f/64.0f) - mean*mean + 1e-5f);
    int c0 = q4*16;
#pragma unroll
    for (int i2 = 0; i2 < 8; i2++) {
        int c = c0 + 2*i2;
        float v0 = (xv[2*i2]   - mean) * inv * g2[c]   + b2[c];
        float v1 = (xv[2*i2+1] - mean) * inv * g2[c+1] + b2[c+1];
        *(unsigned*)&h2[row*72 + c] = packbf(v0, v1);
    }
    __syncthreads();

    int w = t >> 5, lane = t & 31;
    int g = lane >> 2, tt = lane & 3;
    int m0 = (w & 3) * 16, nbase = (w >> 2) * 128;
    int lane15 = lane & 15, hi8 = (lane & 16) ? 8 : 0;
    int l7 = lane & 7, lg8 = (lane >> 3) * 8;
    unsigned ah = sptr(h2), aw = sptr(w1s);

    unsigned qa[4][4];
#pragma unroll
    for (int kc = 0; kc < 4; kc++)
        ldsm4(qa[kc], ah + ((m0+lane15)*72 + kc*16 + hi8)*2);

    float of[16][4] = {};
#pragma unroll
    for (int n = 0; n < 16; n++) {
        int ncol = nbase + n*8;
        unsigned bb[8];
        ldsm4(bb,   aw + ((ncol+l7)*72 + lg8)*2);
        ldsm4(bb+4, aw + ((ncol+l7)*72 + 32 + lg8)*2);
        mma16816(of[n], qa[0], bb[0], bb[1]);
        mma16816(of[n], qa[1], bb[2], bb[3]);
        mma16816(of[n], qa[2], bb[4], bb[5]);
        mma16816(of[n], qa[3], bb[6], bb[7]);
    }
    int grow0 = blockIdx.x*64 + m0 + g;
#pragma unroll
    for (int n = 0; n < 16; n++) {
        int col = nbase + n*8 + 2*tt;
        float2 bv = *(const float2*)(fc1b + col);
        *(unsigned*)&g_fb[(size_t)grow0*256 + col] =
            packbf(of[n][0]+bv.x, of[n][1]+bv.y);
        *(unsigned*)&g_fb[(size_t)(grow0+8)*256 + col] =
            packbf(of[n][2]+bv.x, of[n][3]+bv.y);
    }
}

// ============================================================================
// K6: depthwise 3x3 SAME (fp32 rolling, bf16 in) + GELU -> bf16, fc2 via mma,
// + residual. smem: dws f32 9216 + w2s[64][264] + gg[64][264] bf16 = 76800 B
// ============================================================================
#define FC2_SMEM_BYTES (9216 + (64*264)*2*2)
__global__ void __launch_bounds__(256)
k_dw_fc2(const float* __restrict__ dww, const float* __restrict__ fc2b,
         float* __restrict__ outp) {
    extern __shared__ __align__(16) char smC[];
    float* dws = (float*)smC;                                    // [9][256]
    __nv_bfloat16* w2s = (__nv_bfloat16*)(smC + 9216);           // [cout 64][ci 264]
    __nv_bfloat16* gg  = (__nv_bfloat16*)(smC + 9216 + 64*264*2);// [tok 64][ci 264]
    int t = threadIdx.x;
    for (int i = t; i < 2304; i += 256) dws[i] = dww[i];
    for (int i = t; i < 2048; i += 256) { int r = i>>5, j = (i&31)*8;
        *(uint4*)&w2s[r*264+j] = *(const uint4*)&g_w2T[r*256+j]; }
    __syncthreads();

    int tok0 = blockIdx.x * 64;
    int b = tok0 >> 14; int rem = tok0 & 16383; int y = rem >> 7; int x0 = rem & 127;
    const __nv_bfloat16* fb = g_fb + (size_t)b * NN * HIDN;

    // ---- depthwise conv (rolling column dots) + GELU, t = channel ----
    {
        int ci = t;
        float w00 = dws[0*256+ci], w01 = dws[1*256+ci], w02 = dws[2*256+ci];
        float w10 = dws[3*256+ci], w11 = dws[4*256+ci], w12 = dws[5*256+ci];
        float w20 = dws[6*256+ci], w21 = dws[7*256+ci], w22 = dws[8*256+ci];
        bool y0ok = (y > 0), y2ok = (y < 127);
        float A = 0.f, Bc = 0.f, Cn = 0.f;
        const __nv_bfloat16* fr0 = fb + ((size_t)(y-1)*128)*256 + ci;
        const __nv_bfloat16* fr1 = fb + ((size_t) y   *128)*256 + ci;
        const __nv_bfloat16* fr2 = fb + ((size_t)(y+1)*128)*256 + ci;
#pragma unroll 4
        for (int c = x0-1; c <= x0+64; c++) {
            float a0 = 0.f, a1 = 0.f, a2 = 0.f;
            if ((unsigned)c < 128u) {
                float f0 = y0ok ? __bfloat162float(fr0[(size_t)c*256]) : 0.f;
                float f1 = __bfloat162float(fr1[(size_t)c*256]);
                float f2 = y2ok ? __bfloat162float(fr2[(size_t)c*256]) : 0.f;
                a0 = f0*w00 + f1*w10 + f2*w20;
                a1 = f0*w01 + f1*w11 + f2*w21;
                a2 = f0*w02 + f1*w12 + f2*w22;
            }
            A += a2; Bc += a1; Cn += a0;
            int xo = c - 1;
            if (xo >= x0 && xo < x0 + 64) {
                float v = A;
                float ge = 0.5f * v * (1.0f + erff(v * 0.70710678118654752f));
                gg[(xo - x0)*264 + ci] = __float2bfloat16_rn(ge);
            }
            A = Bc; Bc = Cn; Cn = 0.f;
        }
    }
    __syncthreads();

    // ---- fc2 GEMM via mma + ldmatrix ----
    int w = t >> 5, lane = t & 31;
    int g = lane >> 2, tt = lane & 3;
    int m0 = (w & 3) * 16, nbase = (w >> 2) * 32;
    int lane15 = lane & 15, hi8 = (lane & 16) ? 8 : 0;
    int l7 = lane & 7, lg8 = (lane >> 3) * 8;
    unsigned ag = sptr(gg), aw2 = sptr(w2s);

    float of[4][4] = {};
#pragma unroll
    for (int kc2 = 0; kc2 < 8; kc2++) {
        unsigned A0[4], A1[4];
        ldsm4(A0, ag + ((m0+lane15)*264 + (2*kc2)*16 + hi8)*2);
        ldsm4(A1, ag + ((m0+lane15)*264 + (2*kc2+1)*16 + hi8)*2);
#pragma unroll
        for (int n = 0; n < 4; n++) {
            unsigned bb[4];
            ldsm4(bb, aw2 + ((nbase + n*8 + l7)*264 + (2*kc2)*16 + lg8)*2);
            mma16816(of[n], A0, bb[0], bb[1]);
            mma16816(of[n], A1, bb[2], bb[3]);
        }
    }
    int tok = tok0 + m0 + g;
#pragma unroll
    for (int n = 0; n < 4; n++) {
        int col = nbase + n*8 + 2*tt;
        float2 bv = *(const float2*)(fc2b + col);
        size_t gi0 = (size_t)tok*64 + col;
        float2 xv0 = *(const float2*)(g_x2 + gi0);
        float2 o0; o0.x = xv0.x + of[n][0] + bv.x; o0.y = xv0.y + of[n][1] + bv.y;
        *(float2*)(outp + gi0) = o0;
        size_t gi1 = gi0 + 8*64;
        float2 xv1 = *(const float2*)(g_x2 + gi1);
        float2 o1; o1.x = xv1.x + of[n][2] + bv.x; o1.y = xv1.y + of[n][3] + bv.y;
        *(float2*)(outp + gi1) = o1;
    }
}

// ============================================================================
extern "C" void kernel_launch(void* const* d_in, const int* in_sizes, int n_in,
                              void* d_out, int out_size) {
    const float* x     = (const float*)d_in[0];
    const float* ln1_g = (const float*)d_in[3];
    const float* ln1_b = (const float*)d_in[4];
    const float* q_w   = (const float*)d_in[5];
    const float* q_b   = (const float*)d_in[6];
    const float* kv_w  = (const float*)d_in[7];
    const float* kv_b  = (const float*)d_in[8];
    const float* proj_w= (const float*)d_in[9];
    const float* proj_b= (const float*)d_in[10];
    const float* sr_w  = (const float*)d_in[11];
    const float* sr_b  = (const float*)d_in[12];
    const float* srn_g = (const float*)d_in[13];
    const float* srn_b = (const float*)d_in[14];
    const float* ln2_g = (const float*)d_in[15];
    const float* ln2_b = (const float*)d_in[16];
    const float* fc1_w = (const float*)d_in[17];
    const float* fc1_b = (const float*)d_in[18];
    const float* dw_w  = (const float*)d_in[19];
    const float* fc2_w = (const float*)d_in[20];
    const float* fc2_b = (const float*)d_in[21];
    float* outp = (float*)d_out;

    cudaFuncSetAttribute(k_srconv,  cudaFuncAttributeMaxDynamicSharedMemorySize, SRC_SMEM_BYTES);
    cudaFuncSetAttribute(k_attn,    cudaFuncAttributeMaxDynamicSharedMemorySize, ATTN_SMEM_BYTES);
    cudaFuncSetAttribute(k_ln2_fc1, cudaFuncAttributeMaxDynamicSharedMemorySize, FC1_SMEM_BYTES);
    cudaFuncSetAttribute(k_dw_fc2,  cudaFuncAttributeMaxDynamicSharedMemorySize, FC2_SMEM_BYTES);

    k_prep   <<<1024, 256>>>(q_w, proj_w, fc1_w, fc2_w, sr_w);
    k_ln1_q  <<<BB*NN/64, 128>>>(x, ln1_g, ln1_b, q_b);
    k_srconv <<<64, 256, SRC_SMEM_BYTES>>>(sr_b);
    k_srn_kv <<<BB*NRR/8, 256>>>(srn_g, srn_b, kv_w, kv_b);
    k_attn   <<<dim3(NN/128, BB), 256, ATTN_SMEM_BYTES>>>(x, proj_b);
    k_ln2_fc1<<<BB*NN/64, 256, FC1_SMEM_BYTES>>>(ln2_g, ln2_b, fc1_b);
    k_dw_fc2 <<<BB*NN/64, 256, FC2_SMEM_BYTES>>>(dw_w, fc2_b, outp);
}